// round 15
// baseline (speedup 1.0000x reference)
#include <cuda_runtime.h>
#include <stdint.h>
#include <math.h>

// ---------------------------------------------------------------------------
// InformerEncoder: B=4, L0=2048, C=2, D=512, F=512, H=8, dh=64, EL=3
// Numerics: exact-fp32 model via 3xTF32 (hi/lo split in-kernel), tcgen05 on
// the sm_103a cubin; scalar fallback for the generic sm_103 PTX pass.
// GEMM: single-buffer smem (66KB), 2 CTAs/SM. TMEM alloc permit is
// RELINQUISHED IMMEDIATELY after alloc so co-resident CTAs can allocate and
// overlap (holding it to kernel end serialized CTAs: measured occ 12.8%).
// ---------------------------------------------------------------------------
#define D_MODEL 512
#define BATCH   4
#define LMAX    2048
#define NH      8
#define DH      64
#define UMAX    40
#define NROW    (BATCH*NH)
#define APAD    65

#define FLAG_BIAS 1
#define FLAG_RES  2
#define FLAG_GELU 4
#define FLAG_ELU  8
#define FLAG_CIRC 16

#define GEMM_CHUNK 32
#define TILE_B     16384                 // one 128x32 fp32 tile in bytes
#define GEMM_SMEM  (1024 + 4*TILE_B)     // align slack + 1 buf x 4 tiles
// idesc: dtype f32 | atype tf32 | btype tf32 | N=128 | M=128
#define TC_IDESC ((1u<<4)|(2u<<7)|(2u<<10)|((128u/8)<<17)|((128u/16)<<24))

#if defined(__CUDA_ARCH_FEAT_SM103_ALL)
#define HAS_TCGEN05 1
#else
#define HAS_TCGEN05 0
#endif

// ------------------------- scratch (static device globals) ------------------
__device__ float g_X   [BATCH*LMAX*D_MODEL];
__device__ float g_XN  [BATCH*LMAX*D_MODEL];
__device__ float g_Y   [BATCH*LMAX*D_MODEL];
__device__ float g_Q   [BATCH*LMAX*D_MODEL];
__device__ float g_K   [BATCH*LMAX*D_MODEL];
__device__ float g_V   [BATCH*LMAX*D_MODEL];
__device__ float g_O   [BATCH*LMAX*D_MODEL];
__device__ float g_H1  [BATCH*LMAX*D_MODEL];
__device__ float g_CV  [BATCH*LMAX*D_MODEL];
__device__ float g_WC  [D_MODEL*3*D_MODEL];
__device__ float g_PE  [LMAX*D_MODEL];
__device__ int   g_IDX [3*LMAX*UMAX];
__device__ float g_M   [NROW*LMAX];
__device__ int   g_TOP [NROW*UMAX];
__device__ float g_VM  [NROW*DH];
__device__ float g_PM  [4*NROW*UMAX];
__device__ float g_PS  [4*NROW*UMAX];
__device__ float g_PA  [4*NROW*UMAX*DH];

// ------------------------- threefry2x32 (JAX-compatible) --------------------
__host__ __device__ inline void threefry2x32(uint32_t k0, uint32_t k1,
                                             uint32_t x0, uint32_t x1,
                                             uint32_t* o0, uint32_t* o1)
{
    uint32_t ks0 = k0, ks1 = k1, ks2 = k0 ^ k1 ^ 0x1BD11BDAu;
    uint32_t ks[3] = {ks0, ks1, ks2};
    x0 += ks0; x1 += ks1;
    const int rA[4] = {13, 15, 26, 6};
    const int rB[4] = {17, 29, 16, 24};
    #pragma unroll
    for (int g = 0; g < 5; ++g) {
        const int* r = (g & 1) ? rB : rA;
        #pragma unroll
        for (int i = 0; i < 4; ++i) {
            x0 += x1;
            x1 = (x1 << r[i]) | (x1 >> (32 - r[i]));
            x1 ^= x0;
        }
        x0 += ks[(g + 1) % 3];
        x1 += ks[(g + 2) % 3] + (uint32_t)(g + 1);
    }
    *o0 = x0; *o1 = x1;
}

__global__ void idx_kernel(uint32_t k0, uint32_t k1, int n, unsigned mask,
                           int* __restrict__ idx)
{
    int j = blockIdx.x * blockDim.x + threadIdx.x;
    if (j >= n) return;
    uint32_t o0, o1;
    threefry2x32(k0, k1, 0u, (uint32_t)j, &o0, &o1);
    idx[j] = (int)((o0 ^ o1) & mask);
}

// ------------------------- common helpers -----------------------------------
__device__ __forceinline__ float gelu_exact(float x)
{
    return 0.5f * x * (1.0f + erff(x * 0.70710678118654752f));
}

__device__ __forceinline__ float tf32f(float x)
{
    uint32_t u;
    asm("cvt.rna.tf32.f32 %0, %1;" : "=r"(u) : "f"(x));
    return __uint_as_float(u);
}

__device__ __forceinline__ void split4(float4 v, float4* h, float4* l)
{
    h->x = tf32f(v.x); l->x = tf32f(v.x - h->x);
    h->y = tf32f(v.y); l->y = tf32f(v.y - h->y);
    h->z = tf32f(v.z); l->z = tf32f(v.z - h->z);
    h->w = tf32f(v.w); l->w = tf32f(v.w - h->w);
}

#if HAS_TCGEN05
// ===================== tcgen05 backend (sm_103a target) =====================
__device__ __forceinline__ uint32_t s2u(const void* p)
{
    uint32_t a;
    asm("{ .reg .u64 t; cvta.to.shared.u64 t, %1; cvt.u32.u64 %0, t; }"
        : "=r"(a) : "l"(p));
    return a;
}

__device__ __forceinline__ uint64_t sdesc(uint32_t a)
{
    return (2ULL << 61) | (1ULL << 46) | (64ULL << 32) | (1ULL << 16)
         | (uint64_t)((a >> 4) & 0x3FFF);
}

__device__ __forceinline__ uint32_t swz(uint32_t b)
{
    return b ^ ((b >> 3) & 0x70);
}

__device__ __forceinline__ void tcmma_tf32(uint32_t d, uint64_t a, uint64_t b,
                                           uint32_t idesc, uint32_t en)
{
    asm volatile(
        "{\n\t"
        ".reg .pred p;\n\t"
        "setp.ne.u32 p, %5, 0;\n\t"
        "tcgen05.mma.cta_group::1.kind::tf32 [%0], %1, %2, %3, {%4,%4,%4,%4}, p;\n\t"
        "}"
        :: "r"(d), "l"(a), "l"(b), "r"(idesc), "r"(0u), "r"(en)
        : "memory");
}

__device__ __forceinline__ void tc_commit(uint32_t mbar)
{
    asm volatile(
        "tcgen05.commit.cta_group::1.mbarrier::arrive::one.shared::cluster.b64 [%0];"
        :: "r"(mbar) : "memory");
}

__device__ __forceinline__ void mbar_wait(uint32_t mbar, uint32_t parity)
{
    asm volatile(
        "{\n\t"
        ".reg .pred P;\n\t"
        "W_%=:\n\t"
        "mbarrier.try_wait.parity.shared.b64 P, [%0], %1;\n\t"
        "@!P bra W_%=;\n\t"
        "}"
        :: "r"(mbar), "r"(parity) : "memory");
}

#define TC_LD_X32(r, addr) \
    asm volatile( \
        "tcgen05.ld.sync.aligned.32x32b.x32.b32 " \
        "{%0, %1, %2, %3, %4, %5, %6, %7, " \
        " %8, %9, %10, %11, %12, %13, %14, %15, " \
        " %16, %17, %18, %19, %20, %21, %22, %23, " \
        " %24, %25, %26, %27, %28, %29, %30, %31}, [%32];" \
        : "=r"((r)[0]),  "=r"((r)[1]),  "=r"((r)[2]),  "=r"((r)[3]), \
          "=r"((r)[4]),  "=r"((r)[5]),  "=r"((r)[6]),  "=r"((r)[7]), \
          "=r"((r)[8]),  "=r"((r)[9]),  "=r"((r)[10]), "=r"((r)[11]), \
          "=r"((r)[12]), "=r"((r)[13]), "=r"((r)[14]), "=r"((r)[15]), \
          "=r"((r)[16]), "=r"((r)[17]), "=r"((r)[18]), "=r"((r)[19]), \
          "=r"((r)[20]), "=r"((r)[21]), "=r"((r)[22]), "=r"((r)[23]), \
          "=r"((r)[24]), "=r"((r)[25]), "=r"((r)[26]), "=r"((r)[27]), \
          "=r"((r)[28]), "=r"((r)[29]), "=r"((r)[30]), "=r"((r)[31]) \
        : "r"(addr))

// C = A @ W^T, 3xTF32 (hi/lo split in producer). 128x128 tile, single buffer.
// FLAG_CIRC: A read from X[B,Lc,512] with circular row offset j-1 (j = k/512).
__device__ __forceinline__ void gemm_tile(
    const float* __restrict__ A, const float* __restrict__ W,
    const float* __restrict__ bias, const float* __restrict__ R,
    const float* __restrict__ eg, const float* __restrict__ eb,
    float* __restrict__ C, int N, int K, int flags, int Lc, int bx, int by)
{
    extern __shared__ char dsm[];
    __shared__ uint32_t s_tmem[1];
    __shared__ uint64_t s_mbar[1];

    const int t = threadIdx.x;
    const uint32_t daddr = s2u(dsm);
    const uint32_t aoff  = (1024u - (daddr & 1023u)) & 1023u;
    char* tb = dsm + aoff;
    const uint32_t tb_addr = daddr + aoff;

    const uint32_t ctrl = s2u(s_tmem);
    const uint32_t mb0  = s2u(&s_mbar[0]);

    if (t < 32) {
        asm volatile(
            "tcgen05.alloc.cta_group::1.sync.aligned.shared::cta.b32 [%0], %1;"
            :: "r"(ctrl), "r"(128u) : "memory");
        // release the per-SM alloc permit IMMEDIATELY so co-resident CTAs can
        // allocate and overlap (holding it to the end serializes CTAs).
        asm volatile("tcgen05.relinquish_alloc_permit.cta_group::1.sync.aligned;");
    }
    if (t == 0)
        asm volatile("mbarrier.init.shared.b64 [%0], 1;" :: "r"(mb0) : "memory");
    __syncthreads();
    const uint32_t tmem_base = s_tmem[0];

    const float* Ab  = A + (size_t)by * 128 * K;   // non-circ path
    const float* Wb  = W + (size_t)bx * 128 * K;
    const int growb  = by * 128;

    const int nb = K / GEMM_CHUNK;

    for (int c = 0; c < nb; c++) {
        if (c > 0) mbar_wait(mb0, (uint32_t)((c - 1) & 1));
        const int cbase = c * GEMM_CHUNK;
        #pragma unroll
        for (int i = 0; i < 4; i++) {
            const int idx = t + i * 256;          // 0..1023
            const int row = idx >> 3, c4 = idx & 7;
            const uint32_t off = swz((uint32_t)(row * 128 + c4 * 16));
            float4 av;
            if (flags & FLAG_CIRC) {
                const int grow = growb + row;
                const int bb = grow / Lc, l = grow - bb * Lc;
                const int j = cbase >> 9;         // kernel tap 0..2
                int sr = l + j - 1;
                if (sr < 0) sr += Lc; else if (sr >= Lc) sr -= Lc;
                av = *(const float4*)(A + ((size_t)(bb * Lc + sr)) * 512
                                        + (cbase & 511) + c4 * 4);
            } else {
                av = *(const float4*)(Ab + (size_t)row * K + cbase + c4 * 4);
            }
            const float4 wv = *(const float4*)(Wb + (size_t)row * K + cbase + c4 * 4);
            float4 h, l4;
            split4(av, &h, &l4);
            *(float4*)(tb + off)              = h;
            *(float4*)(tb + TILE_B + off)     = l4;
            split4(wv, &h, &l4);
            *(float4*)(tb + 2 * TILE_B + off) = h;
            *(float4*)(tb + 3 * TILE_B + off) = l4;
        }
        asm volatile("fence.proxy.async.shared::cta;" ::: "memory");
        __syncthreads();
        if (t == 0) {
            const uint64_t dah = sdesc(tb_addr);
            const uint64_t dal = sdesc(tb_addr + TILE_B);
            const uint64_t dwh = sdesc(tb_addr + 2 * TILE_B);
            const uint64_t dwl = sdesc(tb_addr + 3 * TILE_B);
            #pragma unroll
            for (int s = 0; s < 4; s++) {
                const uint32_t en0 = (c == 0 && s == 0) ? 0u : 1u;
                tcmma_tf32(tmem_base, dah + s * 2, dwl + s * 2, TC_IDESC, en0);
                tcmma_tf32(tmem_base, dal + s * 2, dwh + s * 2, TC_IDESC, 1u);
                tcmma_tf32(tmem_base, dah + s * 2, dwh + s * 2, TC_IDESC, 1u);
            }
            tc_commit(mb0);
        }
    }

    mbar_wait(mb0, (uint32_t)((nb - 1) & 1));
    asm volatile("tcgen05.fence::after_thread_sync;" ::: "memory");

    // epilogue: warp w covers rows (w&3)*32+lane, cols (w>>2)*64 .. +63
    const int w = t >> 5, lane = t & 31;
    const int rown = (w & 3) * 32 + lane;
    const int colw = (w >> 2) * 64;
    const size_t grow = (size_t)(by * 128 + rown);

    #pragma unroll
    for (int half = 0; half < 2; half++) {
        uint32_t dr[32];
        TC_LD_X32(dr, tmem_base + colw + half * 32);
        asm volatile("tcgen05.wait::ld.sync.aligned;" ::: "memory");
        const int cb = bx * 128 + colw + half * 32;
        float* crow = C + grow * N + cb;
        const float* rrow = (flags & FLAG_RES) ? (R + grow * N + cb) : nullptr;
        #pragma unroll
        for (int q = 0; q < 8; q++) {
            float v0 = __uint_as_float(dr[q * 4 + 0]);
            float v1 = __uint_as_float(dr[q * 4 + 1]);
            float v2 = __uint_as_float(dr[q * 4 + 2]);
            float v3 = __uint_as_float(dr[q * 4 + 3]);
            if (flags & FLAG_BIAS) {
                float4 bz = *(const float4*)(bias + cb + q * 4);
                v0 += bz.x; v1 += bz.y; v2 += bz.z; v3 += bz.w;
            }
            if (flags & FLAG_RES) {
                float4 rr = *(const float4*)(rrow + q * 4);
                v0 += rr.x; v1 += rr.y; v2 += rr.z; v3 += rr.w;
            }
            if (flags & FLAG_GELU) {
                v0 = gelu_exact(v0); v1 = gelu_exact(v1);
                v2 = gelu_exact(v2); v3 = gelu_exact(v3);
            }
            if (flags & FLAG_ELU) {
                const float cst = 0.9999950000374997f;   // 1/sqrt(1+1e-5)
                float4 gv = *(const float4*)(eg + cb + q * 4);
                float4 ev = *(const float4*)(eb + cb + q * 4);
                v0 = v0 * cst * gv.x + ev.x;
                v1 = v1 * cst * gv.y + ev.y;
                v2 = v2 * cst * gv.z + ev.z;
                v3 = v3 * cst * gv.w + ev.w;
                v0 = v0 > 0.f ? v0 : expm1f(v0);
                v1 = v1 > 0.f ? v1 : expm1f(v1);
                v2 = v2 > 0.f ? v2 : expm1f(v2);
                v3 = v3 > 0.f ? v3 : expm1f(v3);
            }
            *(float4*)(crow + q * 4) = make_float4(v0, v1, v2, v3);
        }
    }

    __syncthreads();
    if (t == 0)
        asm volatile("mbarrier.inval.shared.b64 [%0];" :: "r"(mb0) : "memory");
    if (t < 32)
        asm volatile("tcgen05.dealloc.cta_group::1.sync.aligned.b32 %0, %1;"
                     :: "r"(tmem_base), "r"(128u));
}

#else
// ============ scalar fallback (generic sm_103 PTX pass; never runs) =========
__device__ __forceinline__ void gemm_tile(
    const float* __restrict__ A, const float* __restrict__ W,
    const float* __restrict__ bias, const float* __restrict__ R,
    const float* __restrict__ eg, const float* __restrict__ eb,
    float* __restrict__ C, int N, int K, int flags, int Lc, int bx, int by)
{
    extern __shared__ char dsm[];
    float* As = (float*)dsm;             // [8][128]
    float* Ws = As + 8 * 128;            // [8][128]
    const int t    = threadIdx.x;
    const int tx   = t & 15;
    const int ty   = t >> 4;
    const int lrow = t >> 1;
    const int lseg = (t & 1) << 2;

    const float* Ab = A + (size_t)by * 128 * K;
    const float* Wb = W + (size_t)bx * 128 * K;

    float acc[8][8];
    #pragma unroll
    for (int i = 0; i < 8; i++)
        #pragma unroll
        for (int j = 0; j < 8; j++) acc[i][j] = 0.f;

    for (int k0 = 0; k0 < K; k0 += 8) {
        float4 a4;
        if (flags & FLAG_CIRC) {
            const int grow = by * 128 + lrow;
            const int bb = grow / Lc, l = grow - bb * Lc;
            const int kk = k0 + lseg;
            const int j = kk >> 9;
            int sr = l + j - 1;
            if (sr < 0) sr += Lc; else if (sr >= Lc) sr -= Lc;
            a4 = *(const float4*)(A + ((size_t)(bb * Lc + sr)) * 512 + (kk & 511));
        } else {
            a4 = *(const float4*)(Ab + (size_t)lrow * K + k0 + lseg);
        }
        float4 w4 = *(const float4*)(Wb + (size_t)lrow * K + k0 + lseg);
        As[(lseg + 0) * 128 + lrow] = a4.x;
        As[(lseg + 1) * 128 + lrow] = a4.y;
        As[(lseg + 2) * 128 + lrow] = a4.z;
        As[(lseg + 3) * 128 + lrow] = a4.w;
        Ws[(lseg + 0) * 128 + lrow] = w4.x;
        Ws[(lseg + 1) * 128 + lrow] = w4.y;
        Ws[(lseg + 2) * 128 + lrow] = w4.z;
        Ws[(lseg + 3) * 128 + lrow] = w4.w;
        __syncthreads();
        #pragma unroll
        for (int k = 0; k < 8; k++) {
            float av[8], bv[8];
            #pragma unroll
            for (int i = 0; i < 8; i++) av[i] = As[k * 128 + ty * 8 + i];
            #pragma unroll
            for (int j = 0; j < 8; j++) bv[j] = Ws[k * 128 + tx * 8 + j];
            #pragma unroll
            for (int i = 0; i < 8; i++)
                #pragma unroll
                for (int j = 0; j < 8; j++)
                    acc[i][j] += av[i] * bv[j];
        }
        __syncthreads();
    }

    const int colbase = bx * 128 + tx * 8;
    #pragma unroll
    for (int i = 0; i < 8; i++) {
        size_t row = (size_t)by * 128 + ty * 8 + i;
        #pragma unroll
        for (int jq = 0; jq < 2; jq++) {
            float4 v;
            v.x = acc[i][jq * 4 + 0]; v.y = acc[i][jq * 4 + 1];
            v.z = acc[i][jq * 4 + 2]; v.w = acc[i][jq * 4 + 3];
            const int col = colbase + jq * 4;
            if (flags & FLAG_BIAS) {
                float4 bz = *(const float4*)(bias + col);
                v.x += bz.x; v.y += bz.y; v.z += bz.z; v.w += bz.w;
            }
            if (flags & FLAG_RES) {
                float4 rr = *(const float4*)(R + row * N + col);
                v.x += rr.x; v.y += rr.y; v.z += rr.z; v.w += rr.w;
            }
            if (flags & FLAG_GELU) {
                v.x = gelu_exact(v.x); v.y = gelu_exact(v.y);
                v.z = gelu_exact(v.z); v.w = gelu_exact(v.w);
            }
            if (flags & FLAG_ELU) {
                const float cst = 0.9999950000374997f;
                float4 gv = *(const float4*)(eg + col);
                float4 ev = *(const float4*)(eb + col);
                v.x = v.x * cst * gv.x + ev.x;
                v.y = v.y * cst * gv.y + ev.y;
                v.z = v.z * cst * gv.z + ev.z;
                v.w = v.w * cst * gv.w + ev.w;
                v.x = v.x > 0.f ? v.x : expm1f(v.x);
                v.y = v.y > 0.f ? v.y : expm1f(v.y);
                v.z = v.z > 0.f ? v.z : expm1f(v.z);
                v.w = v.w > 0.f ? v.w : expm1f(v.w);
            }
            *(float4*)(C + row * N + col) = v;
        }
    }
}
#endif  // HAS_TCGEN05

__global__ __launch_bounds__(256, 2)
void sgemm_kernel(const float* __restrict__ A, const float* __restrict__ W,
                  const float* __restrict__ bias, const float* __restrict__ R,
                  const float* __restrict__ eg, const float* __restrict__ eb,
                  float* __restrict__ C, int N, int K, int flags, int Lc)
{
    gemm_tile(A, W, bias, R, eg, eb, C, N, K, flags, Lc,
              blockIdx.x, blockIdx.y);
}

__global__ __launch_bounds__(256, 2)
void qkv_kernel(const float* __restrict__ A,
                const float* __restrict__ wq, const float* __restrict__ wk,
                const float* __restrict__ wv,
                const float* __restrict__ bq, const float* __restrict__ bk,
                const float* __restrict__ bv,
                float* __restrict__ Qo, float* __restrict__ Ko,
                float* __restrict__ Vo, int K)
{
    int which = blockIdx.z;
    const float* W = which == 0 ? wq : (which == 1 ? wk : wv);
    const float* B = which == 0 ? bq : (which == 1 ? bk : bv);
    float*       C = which == 0 ? Qo : (which == 1 ? Ko : Vo);
    gemm_tile(A, W, B, nullptr, nullptr, nullptr, C, 512, K, FLAG_BIAS, 0,
              blockIdx.x, blockIdx.y);
}

// ------------------------- PE table + embedding -----------------------------
// one thread per (l, kk): double sincos on the same fp32 angle
__global__ void pe_kernel(float* __restrict__ PE)
{
    int i = blockIdx.x * blockDim.x + threadIdx.x;
    if (i >= LMAX * 256) return;
    int kk = i & 255;
    int l  = i >> 8;
    float prod = (float)(2 * kk) * -0.017988946039015984f;
    float divf = (float)exp((double)prod);
    float angf = (float)l * divf;
    double s, c;
    sincos((double)angf, &s, &c);
    float* row = PE + ((size_t)l << 9) + 2 * kk;
    row[0] = (float)s;
    row[1] = (float)c;
}

__global__ void embed_kernel(const float* __restrict__ xe,
                             const float* __restrict__ w,
                             const float* __restrict__ PE,
                             float* __restrict__ X)
{
    int i = blockIdx.x * blockDim.x + threadIdx.x;
    if (i >= BATCH * LMAX * D_MODEL) return;
    int d = i & 511;
    int l = (i >> 9) & (LMAX - 1);
    int b = i >> 20;
    float acc = 0.f;
    #pragma unroll
    for (int j = 0; j < 3; j++) {
        int ls = l + j - 1;
        if (ls < 0) ls += LMAX; else if (ls >= LMAX) ls -= LMAX;
        const float* xr = xe + ((size_t)b * LMAX + ls) * 2;
        acc += xr[0] * w[d * 6 + j] + xr[1] * w[d * 6 + 3 + j];
    }
    X[i] = acc + PE[i & (LMAX * D_MODEL - 1)];
}

// ------------------------- M = max_j(Q.K_idx) - sum_j(Q.K_idx)/L -------------
__global__ void msample_kernel(const float* __restrict__ Q,
                               const float* __restrict__ K,
                               const int* __restrict__ idx,
                               float* __restrict__ M, int L, int U)
{
    int w    = (blockIdx.x * blockDim.x + threadIdx.x) >> 5;
    int lane = threadIdx.x & 31;
    int total = NROW * L;
    if (w >= total) return;
    int l = w % L;
    int h = (w / L) % NH;
    int b = w / (L * NH);
    const float* qp = Q + ((size_t)b * L + l) * D_MODEL + h * DH;
    float q0 = qp[lane], q1 = qp[lane + 32];
    float mx = -3.4e38f, sm = 0.f;
    #pragma unroll 4
    for (int j = 0; j < U; j++) {
        int ki = idx[l * U + j];
        const float* kp = K + ((size_t)b * L + ki) * D_MODEL + h * DH;
        float p = q0 * kp[lane] + q1 * kp[lane + 32];
        #pragma unroll
        for (int o = 16; o > 0; o >>= 1) p += __shfl_xor_sync(0xffffffffu, p, o);
        mx = fmaxf(mx, p);
        sm += p;
    }
    if (lane == 0) M[((size_t)b * NH + h) * L + l] = mx - sm / (float)L;
}

// ------------------------- top-u selection (set semantics) ------------------
__global__ void topk_kernel(const float* __restrict__ M, int* __restrict__ top,
                            int L, int U)
{
    __shared__ float vals[LMAX];
    __shared__ unsigned char flags[LMAX];
    __shared__ float rv[256];
    __shared__ int   ri[256];
    int row = blockIdx.x;
    int t   = threadIdx.x;
    const float* mrow = M + (size_t)row * L;
    for (int l = t; l < L; l += 256) { vals[l] = mrow[l]; flags[l] = 0; }
    __syncthreads();
    for (int pass = 0; pass < U; pass++) {
        float bv = -3.4e38f; int bi = 0x7fffffff;
        for (int l = t; l < L; l += 256) {
            if (!flags[l]) {
                float v = vals[l];
                if (v > bv || (v == bv && l < bi)) { bv = v; bi = l; }
            }
        }
        rv[t] = bv; ri[t] = bi;
        __syncthreads();
        for (int s = 128; s > 0; s >>= 1) {
            if (t < s) {
                float ov = rv[t + s]; int oi = ri[t + s];
                if (ov > rv[t] || (ov == rv[t] && oi < ri[t])) { rv[t] = ov; ri[t] = oi; }
            }
            __syncthreads();
        }
        if (t == 0) { top[row * UMAX + pass] = ri[0]; flags[ri[0]] = 1; }
        __syncthreads();
    }
}

// ------------------------- V mean over L ------------------------------------
__global__ void vmean_kernel(const float* __restrict__ V, float* __restrict__ vm,
                             int L)
{
    __shared__ float red[256];
    int row = blockIdx.x;
    int b = row / NH, h = row % NH;
    int t = threadIdx.x;
    int e = t & 63, grp = t >> 6;
    float acc = 0.f;
    for (int l = grp; l < L; l += 4)
        acc += V[((size_t)b * L + l) * D_MODEL + h * DH + e];
    red[t] = acc;
    __syncthreads();
    if (t < 64)
        vm[(size_t)row * DH + t] =
            (red[t] + red[t + 64] + red[t + 128] + red[t + 192]) / (float)L;
}

__global__ void ofill_kernel(const float* __restrict__ vm, float* __restrict__ O,
                             int n, int L)
{
    int i = blockIdx.x * blockDim.x + threadIdx.x;
    if (i >= n) return;
    int d = i & 511;
    int b = i / (L * 512);
    O[i] = vm[(b * NH + (d >> 6)) * 64 + (d & 63)];
}

// ------------------------- flash-style attention ----------------------------
__global__ void attn_kernel(const float* __restrict__ Q,
                            const float* __restrict__ K,
                            const float* __restrict__ V,
                            const int* __restrict__ top,
                            float* __restrict__ PM, float* __restrict__ PS,
                            float* __restrict__ PA,
                            int L, int U, int keys)
{
    extern __shared__ float smf[];
    float* qs = smf;
    float* P  = qs + UMAX * APAD;
    float* Kt = P  + UMAX * APAD;
    float* Vt = Kt + 64 * APAD;
    __shared__ int qidx[UMAX];

    int split = blockIdx.x;
    int row   = blockIdx.y;
    int b = row / NH, h = row % NH;
    int t = threadIdx.x, lane = t & 31, w = t >> 5;

    if (t < U) qidx[t] = top[row * UMAX + t];
    __syncthreads();
    for (int p = t; p < U * 64; p += 256) {
        int j = p >> 6, e = p & 63;
        qs[j * APAD + e] = Q[((size_t)(b * L + qidx[j])) * D_MODEL + h * DH + e];
    }

    float m0[5], s0[5], a0[5], a1[5];
    #pragma unroll
    for (int r = 0; r < 5; r++) { m0[r] = -3.4e38f; s0[r] = 0.f; a0[r] = 0.f; a1[r] = 0.f; }
    __syncthreads();

    int base0 = split * keys;
    int ntile = keys >> 6;
    for (int tl = 0; tl < ntile; tl++) {
        int kb = base0 + (tl << 6);
        for (int i = t; i < 1024; i += 256) {
            int r = i >> 4, c = (i & 15) << 2;
            size_t gi = ((size_t)(b * L + kb + r)) * D_MODEL + h * DH + c;
            float4 kv = *(const float4*)(K + gi);
            float* dk = &Kt[r * APAD + c];
            dk[0] = kv.x; dk[1] = kv.y; dk[2] = kv.z; dk[3] = kv.w;
            float4 vv = *(const float4*)(V + gi);
            float* dv = &Vt[r * APAD + c];
            dv[0] = vv.x; dv[1] = vv.y; dv[2] = vv.z; dv[3] = vv.w;
        }
        __syncthreads();

        {
            float d0[5], d1[5];
            #pragma unroll
            for (int r = 0; r < 5; r++) { d0[r] = 0.f; d1[r] = 0.f; }
            const float* k0 = &Kt[lane * APAD];
            const float* k1 = &Kt[(lane + 32) * APAD];
            #pragma unroll 8
            for (int e = 0; e < 64; e++) {
                float ke0 = k0[e], ke1 = k1[e];
                #pragma unroll
                for (int r = 0; r < 5; r++) {
                    float qe = qs[(w + (r << 3)) * APAD + e];
                    d0[r] += qe * ke0;
                    d1[r] += qe * ke1;
                }
            }
            #pragma unroll
            for (int r = 0; r < 5; r++) {
                int j = w + (r << 3);
                if (j < U) {
                    P[j * APAD + lane]      = d0[r] * 0.125f;
                    P[j * APAD + lane + 32] = d1[r] * 0.125f;
                }
            }
        }
        __syncwarp();

        #pragma unroll
        for (int r = 0; r < 5; r++) {
            int j = w + (r << 3);
            if (j >= U) break;
            float v0 = P[j * APAD + lane], v1 = P[j * APAD + lane + 32];
            float tm = fmaxf(v0, v1);
            #pragma unroll
            for (int o = 16; o > 0; o >>= 1)
                tm = fmaxf(tm, __shfl_xor_sync(0xffffffffu, tm, o));
            float nm = fmaxf(m0[r], tm);
            float p0 = expf(v0 - nm), p1 = expf(v1 - nm);
            float ts = p0 + p1;
            #pragma unroll
            for (int o = 16; o > 0; o >>= 1)
                ts += __shfl_xor_sync(0xffffffffu, ts, o);
            float al = expf(m0[r] - nm);
            s0[r] = s0[r] * al + ts;
            a0[r] *= al; a1[r] *= al;
            m0[r] = nm;
            P[j * APAD + lane]      = p0;
            P[j * APAD + lane + 32] = p1;
        }
        __syncthreads();

        #pragma unroll 4
        for (int k = 0; k < 64; k++) {
            float ve0 = Vt[k * APAD + lane];
            float ve1 = Vt[k * APAD + lane + 32];
            #pragma unroll
            for (int r = 0; r < 5; r++) {
                float pk = P[(w + (r << 3)) * APAD + k];
                a0[r] += pk * ve0;
                a1[r] += pk * ve1;
            }
        }
        __syncthreads();
    }

    #pragma unroll
    for (int r = 0; r < 5; r++) {
        int j = w + (r << 3);
        if (j >= U) break;
        int pidx = (split * NROW + row) * UMAX + j;
        if (lane == 0) { PM[pidx] = m0[r]; PS[pidx] = s0[r]; }
        PA[(size_t)pidx * 64 + lane]      = a0[r];
        PA[(size_t)pidx * 64 + lane + 32] = a1[r];
    }
}

__global__ void attn_merge(const float* __restrict__ PM,
                           const float* __restrict__ PS,
                           const float* __restrict__ PA,
                           const int* __restrict__ top,
                           float* __restrict__ O, int L, int U, int nsplit)
{
    int gw = (blockIdx.x * blockDim.x + threadIdx.x) >> 5;
    int lane = threadIdx.x & 31;
    if (gw >= NROW * U) return;
    int row = gw / U, j = gw % U;
    int b = row / NH, h = row % NH;
    float M = -3.4e38f;
    for (int i = 0; i < nsplit; i++)
        M = fmaxf(M, PM[(i * NROW + row) * UMAX + j]);
    float s = 0.f, acc0 = 0.f, acc1 = 0.f;
    for (int i = 0; i < nsplit; i++) {
        int pidx = (i * NROW + row) * UMAX + j;
        float sc = expf(PM[pidx] - M);
        s    += PS[pidx] * sc;
        acc0 += PA[(size_t)pidx * 64 + lane] * sc;
        acc1 += PA[(size_t)pidx * 64 + lane + 32] * sc;
    }
    float inv = 1.f / s;
    int qi = top[row * UMAX + j];
    size_t o = ((size_t)(b * L + qi)) * D_MODEL + h * DH;
    O[o + lane]      = acc0 * inv;
    O[o + lane + 32] = acc1 * inv;
}

// ------------------------- LayerNorm (two-pass variance) --------------------
__global__ void ln_kernel(const float* __restrict__ X, const float* __restrict__ g,
                          const float* __restrict__ b, float* __restrict__ Y)
{
    __shared__ float s1[4], s2[4];
    int row = blockIdx.x, t = threadIdx.x;
    const float4 v = ((const float4*)(X + (size_t)row * D_MODEL))[t];
    float s = v.x + v.y + v.z + v.w;
    #pragma unroll
    for (int o = 16; o > 0; o >>= 1) s += __shfl_xor_sync(0xffffffffu, s, o);
    if ((t & 31) == 0) s1[t >> 5] = s;
    __syncthreads();
    float mean = (s1[0] + s1[1] + s1[2] + s1[3]) * (1.f / 512.f);
    float dx = v.x - mean, dy = v.y - mean, dz = v.z - mean, dw = v.w - mean;
    float ss = dx * dx + dy * dy + dz * dz + dw * dw;
    #pragma unroll
    for (int o = 16; o > 0; o >>= 1) ss += __shfl_xor_sync(0xffffffffu, ss, o);
    if ((t & 31) == 0) s2[t >> 5] = ss;
    __syncthreads();
    float var = (s2[0] + s2[1] + s2[2] + s2[3]) * (1.f / 512.f);
    float inv = 1.f / sqrtf(var + 1e-5f);
    const float4 g4 = ((const float4*)g)[t];
    const float4 b4 = ((const float4*)b)[t];
    float4 o;
    o.x = dx * inv * g4.x + b4.x;
    o.y = dy * inv * g4.y + b4.y;
    o.z = dz * inv * g4.z + b4.z;
    o.w = dw * inv * g4.w + b4.w;
    ((float4*)(Y + (size_t)row * D_MODEL))[t] = o;
}

// ------------------------- conv-distill helpers -----------------------------
// weight relayout: WC[n][j*512+c] = cv_w[n][c][j]
__global__ void wtrans_kernel(const float* __restrict__ cv, float* __restrict__ WC)
{
    int i = blockIdx.x * blockDim.x + threadIdx.x;
    if (i >= D_MODEL * 3 * D_MODEL) return;
    int n = i / 1536, k = i % 1536;
    int j = k / 512, c = k % 512;
    WC[i] = cv[(size_t)n * 1536 + c * 3 + j];
}

__global__ void pool_kernel(const float* __restrict__ Y, float* __restrict__ X,
                            int L)
{
    int Lh = L >> 1;
    int i = blockIdx.x * blockDim.x + threadIdx.x;
    if (i >= BATCH * Lh * 512) return;
    int d = i & 511;
    int m = (i >> 9) % Lh;
    int b = i / (Lh * 512);
    const float* yb = Y + (size_t)b * L * 512 + d;
    float v = fmaxf(yb[(size_t)(2 * m) * 512], yb[(size_t)(2 * m + 1) * 512]);
    if (m > 0) v = fmaxf(v, yb[(size_t)(2 * m - 1) * 512]);
    X[i] = v;
}

// ---------------------------------------------------------------------------
extern "C" void kernel_launch(void* const* d_in, const int* in_sizes, int n_in,
                              void* d_out, int out_size)
{
    (void)in_sizes; (void)n_in; (void)out_size;
    const float* x_enc = (const float*)d_in[0];
    const float* emb_w = (const float*)d_in[1];
    const float* Wq  = (const float*)d_in[2];
    const float* bq  = (const float*)d_in[3];
    const float* Wk  = (const float*)d_in[4];
    const float* bk  = (const float*)d_in[5];
    const float* Wv  = (const float*)d_in[6];
    const float* bv  = (const float*)d_in[7];
    const float* Wo  = (const float*)d_in[8];
    const float* bo  = (const float*)d_in[9];
    const float* ln1g = (const float*)d_in[10];
    const float* ln1b = (const float*)d_in[11];
    const float* W1  = (const float*)d_in[12];
    const float* b1  = (const float*)d_in[13];
    const float* W2  = (const float*)d_in[14];
    const float* b2  = (const float*)d_in[15];
    const float* ln2g = (const float*)d_in[16];
    const float* ln2b = (const float*)d_in[17];
    const float* cvw = (const float*)d_in[18];
    const float* cvb = (const float*)d_in[19];
    const float* bng = (const float*)d_in[20];
    const float* bnb = (const float*)d_in[21];
    const float* ngp = (const float*)d_in[22];
    const float* nbp = (const float*)d_in[23];

    float *X, *XN, *Yb, *Qb, *Kb, *Vb, *Ob, *H1b, *CVb, *WCb;
    float *PEb, *Mb, *VMb, *PMb, *PSb, *PAb;
    int *IDXb, *TOPb;
    cudaGetSymbolAddress((void**)&X,    g_X);
    cudaGetSymbolAddress((void**)&XN,   g_XN);
    cudaGetSymbolAddress((void**)&Yb,   g_Y);
    cudaGetSymbolAddress((void**)&Qb,   g_Q);
    cudaGetSymbolAddress((void**)&Kb,   g_K);
    cudaGetSymbolAddress((void**)&Vb,   g_V);
    cudaGetSymbolAddress((void**)&Ob,   g_O);
    cudaGetSymbolAddress((void**)&H1b,  g_H1);
    cudaGetSymbolAddress((void**)&CVb,  g_CV);
    cudaGetSymbolAddress((void**)&WCb,  g_WC);
    cudaGetSymbolAddress((void**)&PEb,  g_PE);
    cudaGetSymbolAddress((void**)&Mb,   g_M);
    cudaGetSymbolAddress((void**)&VMb,  g_VM);
    cudaGetSymbolAddress((void**)&PMb,  g_PM);
    cudaGetSymbolAddress((void**)&PSb,  g_PS);
    cudaGetSymbolAddress((void**)&PAb,  g_PA);
    cudaGetSymbolAddress((void**)&IDXb, g_IDX);
    cudaGetSymbolAddress((void**)&TOPb, g_TOP);

    const int attn_smem = (UMAX * APAD * 2 + 64 * APAD * 2) * 4;
    cudaFuncSetAttribute(attn_kernel,
                         cudaFuncAttributeMaxDynamicSharedMemorySize, attn_smem);
    cudaFuncSetAttribute(sgemm_kernel,
                         cudaFuncAttributeMaxDynamicSharedMemorySize, GEMM_SMEM);
    cudaFuncSetAttribute(qkv_kernel,
                         cudaFuncAttributeMaxDynamicSharedMemorySize, GEMM_SMEM);

    // launch order: pe(0), embed(1), idx0(2), qkv(3)... so the profiler's
    // fixed capture slot lands on the tcgen05 GEMM.
    pe_kernel<<<(LMAX * 256 + 255) / 256, 256>>>(PEb);
    {
        int total = BATCH * LMAX * D_MODEL;
        embed_kernel<<<(total + 255) / 256, 256>>>(x_enc, emb_w, PEb, X);
    }

    int Ls[3] = {2048, 1024, 512};
    int Us[3] = {40, 35, 35};
    // idx for layer 0 only (needed before layer-0 msample)
    {
        uint32_t f0, f1, k2a, k2b;
        threefry2x32(0u, 42u, 0u, 0u, &f0, &f1);
        threefry2x32(f0, f1, 0u, 1u, &k2a, &k2b);
        int nidx = Ls[0] * Us[0];
        idx_kernel<<<(nidx + 255) / 256, 256>>>(k2a, k2b, nidx,
                                                (unsigned)(Ls[0] - 1), IDXb);
    }

    int L = LMAX;
    for (int layer = 0; layer < 3; layer++) {
        int U = Us[layer];
        int Mrows = BATCH * L;
        dim3 gg(D_MODEL / 128, Mrows / 128);

        const float* wq = Wq + (size_t)layer * 512 * 512;
        const float* wk = Wk + (size_t)layer * 512 * 512;
        const float* wv = Wv + (size_t)layer * 512 * 512;
        const float* wo = Wo + (size_t)layer * 512 * 512;
        const float* w1 = W1 + (size_t)layer * 512 * 512;
        const float* w2 = W2 + (size_t)layer * 512 * 512;
        const int* idxp = IDXb + layer * LMAX * UMAX;

        {
            dim3 gq(D_MODEL / 128, Mrows / 128, 3);
            qkv_kernel<<<gq, 256, GEMM_SMEM>>>(X, wq, wk, wv,
                                               bq + layer * 512, bk + layer * 512,
                                               bv + layer * 512, Qb, Kb, Vb, 512);
        }

        // prefetch idx for the next layers (after layer-0 qkv)
        if (layer == 0) {
            for (int lay = 1; lay < 3; lay++) {
                uint32_t f0, f1, k2a, k2b;
                threefry2x32(0u, 42u, 0u, (uint32_t)lay, &f0, &f1);
                threefry2x32(f0, f1, 0u, 1u, &k2a, &k2b);
                int nidx = Ls[lay] * Us[lay];
                idx_kernel<<<(nidx + 255) / 256, 256>>>(
                    k2a, k2b, nidx, (unsigned)(Ls[lay] - 1),
                    IDXb + lay * LMAX * UMAX);
            }
        }

        int warps = NROW * L;
        msample_kernel<<<(warps * 32 + 255) / 256, 256>>>(Qb, Kb, idxp, Mb, L, U);
        topk_kernel<<<NROW, 256>>>(Mb, TOPb, L, U);
        vmean_kernel<<<NROW, 256>>>(Vb, VMb, L);
        ofill_kernel<<<(Mrows * 512 + 255) / 256, 256>>>(VMb, Ob, Mrows * 512, L);

        {
            int keys = 512;
            int nsplit = L / keys;
            dim3 ag(nsplit, NROW);
            attn_kernel<<<ag, 256, attn_smem>>>(Qb, Kb, Vb, TOPb,
                                                PMb, PSb, PAb, L, U, keys);
            int mw = NROW * U;
            attn_merge<<<(mw * 32 + 255) / 256, 256>>>(PMb, PSb, PAb, TOPb,
                                                       Ob, L, U, nsplit);
        }

        sgemm_kernel<<<gg, 256, GEMM_SMEM>>>(Ob, wo, bo + layer * 512, X,
                                             nullptr, nullptr, Yb, 512, 512,
                                             FLAG_BIAS | FLAG_RES, 0);
        ln_kernel<<<Mrows, 128>>>(Yb, ln1g + layer * 512, ln1b + layer * 512, XN);
        sgemm_kernel<<<gg, 256, GEMM_SMEM>>>(XN, w1, b1 + layer * 512, nullptr,
                                             nullptr, nullptr, H1b, 512, 512,
                                             FLAG_BIAS | FLAG_GELU, 0);
        sgemm_kernel<<<gg, 256, GEMM_SMEM>>>(H1b, w2, b2 + layer * 512, XN,
                                             nullptr, nullptr, Yb, 512, 512,
                                             FLAG_BIAS | FLAG_RES, 0);
        ln_kernel<<<Mrows, 128>>>(Yb, ln2g + layer * 512, ln2b + layer * 512, X);

        if (layer < 2) {
            wtrans_kernel<<<(512 * 1536 + 255) / 256, 256>>>(
                cvw + (size_t)layer * 512 * 1536, WCb);
            sgemm_kernel<<<gg, 256, GEMM_SMEM>>>(X, WCb, cvb + layer * 512,
                                                 nullptr, bng + layer * 512,
                                                 bnb + layer * 512, CVb, 512, 1536,
                                                 FLAG_BIAS | FLAG_ELU | FLAG_CIRC, L);
            int Lh = L / 2;
            pool_kernel<<<(BATCH * Lh * 512 + 255) / 256, 256>>>(CVb, X, L);
            L = Lh;
        }
    }

    ln_kernel<<<BATCH * L, 128>>>(X, ngp, nbp, (float*)d_out);
}

// round 16
// speedup vs baseline: 1.2385x; 1.2385x over previous
#include <cuda_runtime.h>
#include <stdint.h>
#include <math.h>

// ---------------------------------------------------------------------------
// InformerEncoder: B=4, L0=2048, C=2, D=512, F=512, H=8, dh=64, EL=3
// Numerics: exact-fp32 model via 3xTF32 (hi/lo split in-kernel), tcgen05 on
// the sm_103a cubin; scalar fallback for the generic sm_103 PTX pass.
// GEMM: DOUBLE-buffered smem (129KB, 1 CTA/SM): producer of chunk c+1 runs
// under the async mma of chunk c. Alloc permit relinquished at END (R13
// proven; early release caused cross-CTA port thrash, R14 regression).
// ---------------------------------------------------------------------------
#define D_MODEL 512
#define BATCH   4
#define LMAX    2048
#define NH      8
#define DH      64
#define UMAX    40
#define NROW    (BATCH*NH)
#define APAD    65

#define FLAG_BIAS 1
#define FLAG_RES  2
#define FLAG_GELU 4
#define FLAG_ELU  8
#define FLAG_CIRC 16

#define GEMM_CHUNK 32
#define TILE_B     16384                 // one 128x32 fp32 tile in bytes
#define GEMM_SMEM  (1024 + 8*TILE_B)     // align slack + 2 bufs x 4 tiles
// idesc: dtype f32 | atype tf32 | btype tf32 | N=128 | M=128
#define TC_IDESC ((1u<<4)|(2u<<7)|(2u<<10)|((128u/8)<<17)|((128u/16)<<24))

#if defined(__CUDA_ARCH_FEAT_SM103_ALL)
#define HAS_TCGEN05 1
#else
#define HAS_TCGEN05 0
#endif

// ------------------------- scratch (static device globals) ------------------
__device__ float g_X   [BATCH*LMAX*D_MODEL];
__device__ float g_XN  [BATCH*LMAX*D_MODEL];
__device__ float g_Y   [BATCH*LMAX*D_MODEL];
__device__ float g_Q   [BATCH*LMAX*D_MODEL];
__device__ float g_K   [BATCH*LMAX*D_MODEL];
__device__ float g_V   [BATCH*LMAX*D_MODEL];
__device__ float g_O   [BATCH*LMAX*D_MODEL];
__device__ float g_H1  [BATCH*LMAX*D_MODEL];
__device__ float g_CV  [BATCH*LMAX*D_MODEL];
__device__ float g_WC  [D_MODEL*3*D_MODEL];
__device__ float g_PE  [LMAX*D_MODEL];
__device__ int   g_IDX [3*LMAX*UMAX];
__device__ float g_M   [NROW*LMAX];
__device__ int   g_TOP [NROW*UMAX];
__device__ float g_VM  [NROW*DH];
__device__ float g_PM  [4*NROW*UMAX];
__device__ float g_PS  [4*NROW*UMAX];
__device__ float g_PA  [4*NROW*UMAX*DH];

// ------------------------- threefry2x32 (JAX-compatible) --------------------
__host__ __device__ inline void threefry2x32(uint32_t k0, uint32_t k1,
                                             uint32_t x0, uint32_t x1,
                                             uint32_t* o0, uint32_t* o1)
{
    uint32_t ks0 = k0, ks1 = k1, ks2 = k0 ^ k1 ^ 0x1BD11BDAu;
    uint32_t ks[3] = {ks0, ks1, ks2};
    x0 += ks0; x1 += ks1;
    const int rA[4] = {13, 15, 26, 6};
    const int rB[4] = {17, 29, 16, 24};
    #pragma unroll
    for (int g = 0; g < 5; ++g) {
        const int* r = (g & 1) ? rB : rA;
        #pragma unroll
        for (int i = 0; i < 4; ++i) {
            x0 += x1;
            x1 = (x1 << r[i]) | (x1 >> (32 - r[i]));
            x1 ^= x0;
        }
        x0 += ks[(g + 1) % 3];
        x1 += ks[(g + 2) % 3] + (uint32_t)(g + 1);
    }
    *o0 = x0; *o1 = x1;
}

__global__ void idx_kernel(uint32_t k0, uint32_t k1, int n, unsigned mask,
                           int* __restrict__ idx)
{
    int j = blockIdx.x * blockDim.x + threadIdx.x;
    if (j >= n) return;
    uint32_t o0, o1;
    threefry2x32(k0, k1, 0u, (uint32_t)j, &o0, &o1);
    idx[j] = (int)((o0 ^ o1) & mask);
}

// ------------------------- common helpers -----------------------------------
__device__ __forceinline__ float gelu_exact(float x)
{
    return 0.5f * x * (1.0f + erff(x * 0.70710678118654752f));
}

__device__ __forceinline__ float tf32f(float x)
{
    uint32_t u;
    asm("cvt.rna.tf32.f32 %0, %1;" : "=r"(u) : "f"(x));
    return __uint_as_float(u);
}

__device__ __forceinline__ void split4(float4 v, float4* h, float4* l)
{
    h->x = tf32f(v.x); l->x = tf32f(v.x - h->x);
    h->y = tf32f(v.y); l->y = tf32f(v.y - h->y);
    h->z = tf32f(v.z); l->z = tf32f(v.z - h->z);
    h->w = tf32f(v.w); l->w = tf32f(v.w - h->w);
}

#if HAS_TCGEN05
// ===================== tcgen05 backend (sm_103a target) =====================
__device__ __forceinline__ uint32_t s2u(const void* p)
{
    uint32_t a;
    asm("{ .reg .u64 t; cvta.to.shared.u64 t, %1; cvt.u32.u64 %0, t; }"
        : "=r"(a) : "l"(p));
    return a;
}

__device__ __forceinline__ uint64_t sdesc(uint32_t a)
{
    return (2ULL << 61) | (1ULL << 46) | (64ULL << 32) | (1ULL << 16)
         | (uint64_t)((a >> 4) & 0x3FFF);
}

__device__ __forceinline__ uint32_t swz(uint32_t b)
{
    return b ^ ((b >> 3) & 0x70);
}

__device__ __forceinline__ void tcmma_tf32(uint32_t d, uint64_t a, uint64_t b,
                                           uint32_t idesc, uint32_t en)
{
    asm volatile(
        "{\n\t"
        ".reg .pred p;\n\t"
        "setp.ne.u32 p, %5, 0;\n\t"
        "tcgen05.mma.cta_group::1.kind::tf32 [%0], %1, %2, %3, {%4,%4,%4,%4}, p;\n\t"
        "}"
        :: "r"(d), "l"(a), "l"(b), "r"(idesc), "r"(0u), "r"(en)
        : "memory");
}

__device__ __forceinline__ void tc_commit(uint32_t mbar)
{
    asm volatile(
        "tcgen05.commit.cta_group::1.mbarrier::arrive::one.shared::cluster.b64 [%0];"
        :: "r"(mbar) : "memory");
}

__device__ __forceinline__ void mbar_wait(uint32_t mbar, uint32_t parity)
{
    asm volatile(
        "{\n\t"
        ".reg .pred P;\n\t"
        "W_%=:\n\t"
        "mbarrier.try_wait.parity.shared.b64 P, [%0], %1;\n\t"
        "@!P bra W_%=;\n\t"
        "}"
        :: "r"(mbar), "r"(parity) : "memory");
}

#define TC_LD_X32(r, addr) \
    asm volatile( \
        "tcgen05.ld.sync.aligned.32x32b.x32.b32 " \
        "{%0, %1, %2, %3, %4, %5, %6, %7, " \
        " %8, %9, %10, %11, %12, %13, %14, %15, " \
        " %16, %17, %18, %19, %20, %21, %22, %23, " \
        " %24, %25, %26, %27, %28, %29, %30, %31}, [%32];" \
        : "=r"((r)[0]),  "=r"((r)[1]),  "=r"((r)[2]),  "=r"((r)[3]), \
          "=r"((r)[4]),  "=r"((r)[5]),  "=r"((r)[6]),  "=r"((r)[7]), \
          "=r"((r)[8]),  "=r"((r)[9]),  "=r"((r)[10]), "=r"((r)[11]), \
          "=r"((r)[12]), "=r"((r)[13]), "=r"((r)[14]), "=r"((r)[15]), \
          "=r"((r)[16]), "=r"((r)[17]), "=r"((r)[18]), "=r"((r)[19]), \
          "=r"((r)[20]), "=r"((r)[21]), "=r"((r)[22]), "=r"((r)[23]), \
          "=r"((r)[24]), "=r"((r)[25]), "=r"((r)[26]), "=r"((r)[27]), \
          "=r"((r)[28]), "=r"((r)[29]), "=r"((r)[30]), "=r"((r)[31]) \
        : "r"(addr))

// C = A @ W^T, 3xTF32 (hi/lo split in producer). 128x128 tile, DOUBLE buffer:
// producer of chunk c+1 overlaps the async mma of chunk c.
// FLAG_CIRC: A read from X[B,Lc,512] with circular row offset j-1 (j = k/512).
__device__ __forceinline__ void gemm_tile(
    const float* __restrict__ A, const float* __restrict__ W,
    const float* __restrict__ bias, const float* __restrict__ R,
    const float* __restrict__ eg, const float* __restrict__ eb,
    float* __restrict__ C, int N, int K, int flags, int Lc, int bx, int by)
{
    extern __shared__ char dsm[];
    __shared__ uint32_t s_tmem[1];
    __shared__ uint64_t s_mbar[2];

    const int t = threadIdx.x;
    const uint32_t daddr = s2u(dsm);
    const uint32_t aoff  = (1024u - (daddr & 1023u)) & 1023u;
    char* tb = dsm + aoff;
    const uint32_t tb_addr = daddr + aoff;

    const uint32_t ctrl = s2u(s_tmem);
    const uint32_t mb0  = s2u(&s_mbar[0]);
    const uint32_t mb1  = s2u(&s_mbar[1]);

    if (t < 32)
        asm volatile(
            "tcgen05.alloc.cta_group::1.sync.aligned.shared::cta.b32 [%0], %1;"
            :: "r"(ctrl), "r"(128u) : "memory");
    if (t == 0) {
        asm volatile("mbarrier.init.shared.b64 [%0], 1;" :: "r"(mb0) : "memory");
        asm volatile("mbarrier.init.shared.b64 [%0], 1;" :: "r"(mb1) : "memory");
    }
    __syncthreads();
    const uint32_t tmem_base = s_tmem[0];

    const float* Ab  = A + (size_t)by * 128 * K;   // non-circ path
    const float* Wb  = W + (size_t)bx * 128 * K;
    const int growb  = by * 128;

    const int nb = K / GEMM_CHUNK;
    int ph0 = 0, ph1 = 0;

    for (int c = 0; c < nb; c++) {
        const int buf = c & 1;
        if (c >= 2) {
            if (buf == 0) { mbar_wait(mb0, (uint32_t)(ph0 & 1)); ph0++; }
            else          { mbar_wait(mb1, (uint32_t)(ph1 & 1)); ph1++; }
        }
        const int cbase = c * GEMM_CHUNK;
        char* bufp = tb + buf * (4 * TILE_B);
        #pragma unroll
        for (int i = 0; i < 4; i++) {
            const int idx = t + i * 256;          // 0..1023
            const int row = idx >> 3, c4 = idx & 7;
            const uint32_t off = swz((uint32_t)(row * 128 + c4 * 16));
            float4 av;
            if (flags & FLAG_CIRC) {
                const int grow = growb + row;
                const int bb = grow / Lc, l = grow - bb * Lc;
                const int j = cbase >> 9;         // kernel tap 0..2
                int sr = l + j - 1;
                if (sr < 0) sr += Lc; else if (sr >= Lc) sr -= Lc;
                av = *(const float4*)(A + ((size_t)(bb * Lc + sr)) * 512
                                        + (cbase & 511) + c4 * 4);
            } else {
                av = *(const float4*)(Ab + (size_t)row * K + cbase + c4 * 4);
            }
            const float4 wv = *(const float4*)(Wb + (size_t)row * K + cbase + c4 * 4);
            float4 h, l4;
            split4(av, &h, &l4);
            *(float4*)(bufp + off)              = h;
            *(float4*)(bufp + TILE_B + off)     = l4;
            split4(wv, &h, &l4);
            *(float4*)(bufp + 2 * TILE_B + off) = h;
            *(float4*)(bufp + 3 * TILE_B + off) = l4;
        }
        asm volatile("fence.proxy.async.shared::cta;" ::: "memory");
        __syncthreads();
        if (t == 0) {
            const uint32_t ba = tb_addr + buf * (4 * TILE_B);
            const uint64_t dah = sdesc(ba);
            const uint64_t dal = sdesc(ba + TILE_B);
            const uint64_t dwh = sdesc(ba + 2 * TILE_B);
            const uint64_t dwl = sdesc(ba + 3 * TILE_B);
            #pragma unroll
            for (int s = 0; s < 4; s++) {
                const uint32_t en0 = (c == 0 && s == 0) ? 0u : 1u;
                tcmma_tf32(tmem_base, dah + s * 2, dwl + s * 2, TC_IDESC, en0);
                tcmma_tf32(tmem_base, dal + s * 2, dwh + s * 2, TC_IDESC, 1u);
                tcmma_tf32(tmem_base, dah + s * 2, dwh + s * 2, TC_IDESC, 1u);
            }
            tc_commit(buf ? mb1 : mb0);
        }
        // no wait here: producer for chunk c+1 overlaps mma of chunk c
    }

    mbar_wait(mb0, (uint32_t)(ph0 & 1));
    if (nb >= 2) mbar_wait(mb1, (uint32_t)(ph1 & 1));
    asm volatile("tcgen05.fence::after_thread_sync;" ::: "memory");

    // epilogue: warp w covers rows (w&3)*32+lane, cols (w>>2)*64 .. +63
    const int w = t >> 5, lane = t & 31;
    const int rown = (w & 3) * 32 + lane;
    const int colw = (w >> 2) * 64;
    const size_t grow = (size_t)(by * 128 + rown);

    #pragma unroll
    for (int half = 0; half < 2; half++) {
        uint32_t dr[32];
        TC_LD_X32(dr, tmem_base + colw + half * 32);
        asm volatile("tcgen05.wait::ld.sync.aligned;" ::: "memory");
        const int cb = bx * 128 + colw + half * 32;
        float* crow = C + grow * N + cb;
        const float* rrow = (flags & FLAG_RES) ? (R + grow * N + cb) : nullptr;
        #pragma unroll
        for (int q = 0; q < 8; q++) {
            float v0 = __uint_as_float(dr[q * 4 + 0]);
            float v1 = __uint_as_float(dr[q * 4 + 1]);
            float v2 = __uint_as_float(dr[q * 4 + 2]);
            float v3 = __uint_as_float(dr[q * 4 + 3]);
            if (flags & FLAG_BIAS) {
                float4 bz = *(const float4*)(bias + cb + q * 4);
                v0 += bz.x; v1 += bz.y; v2 += bz.z; v3 += bz.w;
            }
            if (flags & FLAG_RES) {
                float4 rr = *(const float4*)(rrow + q * 4);
                v0 += rr.x; v1 += rr.y; v2 += rr.z; v3 += rr.w;
            }
            if (flags & FLAG_GELU) {
                v0 = gelu_exact(v0); v1 = gelu_exact(v1);
                v2 = gelu_exact(v2); v3 = gelu_exact(v3);
            }
            if (flags & FLAG_ELU) {
                const float cst = 0.9999950000374997f;   // 1/sqrt(1+1e-5)
                float4 gv = *(const float4*)(eg + cb + q * 4);
                float4 ev = *(const float4*)(eb + cb + q * 4);
                v0 = v0 * cst * gv.x + ev.x;
                v1 = v1 * cst * gv.y + ev.y;
                v2 = v2 * cst * gv.z + ev.z;
                v3 = v3 * cst * gv.w + ev.w;
                v0 = v0 > 0.f ? v0 : expm1f(v0);
                v1 = v1 > 0.f ? v1 : expm1f(v1);
                v2 = v2 > 0.f ? v2 : expm1f(v2);
                v3 = v3 > 0.f ? v3 : expm1f(v3);
            }
            *(float4*)(crow + q * 4) = make_float4(v0, v1, v2, v3);
        }
    }

    __syncthreads();
    if (t == 0) {
        asm volatile("mbarrier.inval.shared.b64 [%0];" :: "r"(mb0) : "memory");
        asm volatile("mbarrier.inval.shared.b64 [%0];" :: "r"(mb1) : "memory");
    }
    if (t < 32) {
        asm volatile("tcgen05.relinquish_alloc_permit.cta_group::1.sync.aligned;");
        asm volatile("tcgen05.dealloc.cta_group::1.sync.aligned.b32 %0, %1;"
                     :: "r"(tmem_base), "r"(128u));
    }
}

#else
// ============ scalar fallback (generic sm_103 PTX pass; never runs) =========
__device__ __forceinline__ void gemm_tile(
    const float* __restrict__ A, const float* __restrict__ W,
    const float* __restrict__ bias, const float* __restrict__ R,
    const float* __restrict__ eg, const float* __restrict__ eb,
    float* __restrict__ C, int N, int K, int flags, int Lc, int bx, int by)
{
    extern __shared__ char dsm[];
    float* As = (float*)dsm;             // [8][128]
    float* Ws = As + 8 * 128;            // [8][128]
    const int t    = threadIdx.x;
    const int tx   = t & 15;
    const int ty   = t >> 4;
    const int lrow = t >> 1;
    const int lseg = (t & 1) << 2;

    const float* Ab = A + (size_t)by * 128 * K;
    const float* Wb = W + (size_t)bx * 128 * K;

    float acc[8][8];
    #pragma unroll
    for (int i = 0; i < 8; i++)
        #pragma unroll
        for (int j = 0; j < 8; j++) acc[i][j] = 0.f;

    for (int k0 = 0; k0 < K; k0 += 8) {
        float4 a4;
        if (flags & FLAG_CIRC) {
            const int grow = by * 128 + lrow;
            const int bb = grow / Lc, l = grow - bb * Lc;
            const int kk = k0 + lseg;
            const int j = kk >> 9;
            int sr = l + j - 1;
            if (sr < 0) sr += Lc; else if (sr >= Lc) sr -= Lc;
            a4 = *(const float4*)(A + ((size_t)(bb * Lc + sr)) * 512 + (kk & 511));
        } else {
            a4 = *(const float4*)(Ab + (size_t)lrow * K + k0 + lseg);
        }
        float4 w4 = *(const float4*)(Wb + (size_t)lrow * K + k0 + lseg);
        As[(lseg + 0) * 128 + lrow] = a4.x;
        As[(lseg + 1) * 128 + lrow] = a4.y;
        As[(lseg + 2) * 128 + lrow] = a4.z;
        As[(lseg + 3) * 128 + lrow] = a4.w;
        Ws[(lseg + 0) * 128 + lrow] = w4.x;
        Ws[(lseg + 1) * 128 + lrow] = w4.y;
        Ws[(lseg + 2) * 128 + lrow] = w4.z;
        Ws[(lseg + 3) * 128 + lrow] = w4.w;
        __syncthreads();
        #pragma unroll
        for (int k = 0; k < 8; k++) {
            float av[8], bv[8];
            #pragma unroll
            for (int i = 0; i < 8; i++) av[i] = As[k * 128 + ty * 8 + i];
            #pragma unroll
            for (int j = 0; j < 8; j++) bv[j] = Ws[k * 128 + tx * 8 + j];
            #pragma unroll
            for (int i = 0; i < 8; i++)
                #pragma unroll
                for (int j = 0; j < 8; j++)
                    acc[i][j] += av[i] * bv[j];
        }
        __syncthreads();
    }

    const int colbase = bx * 128 + tx * 8;
    #pragma unroll
    for (int i = 0; i < 8; i++) {
        size_t row = (size_t)by * 128 + ty * 8 + i;
        #pragma unroll
        for (int jq = 0; jq < 2; jq++) {
            float4 v;
            v.x = acc[i][jq * 4 + 0]; v.y = acc[i][jq * 4 + 1];
            v.z = acc[i][jq * 4 + 2]; v.w = acc[i][jq * 4 + 3];
            const int col = colbase + jq * 4;
            if (flags & FLAG_BIAS) {
                float4 bz = *(const float4*)(bias + col);
                v.x += bz.x; v.y += bz.y; v.z += bz.z; v.w += bz.w;
            }
            if (flags & FLAG_RES) {
                float4 rr = *(const float4*)(R + row * N + col);
                v.x += rr.x; v.y += rr.y; v.z += rr.z; v.w += rr.w;
            }
            if (flags & FLAG_GELU) {
                v.x = gelu_exact(v.x); v.y = gelu_exact(v.y);
                v.z = gelu_exact(v.z); v.w = gelu_exact(v.w);
            }
            if (flags & FLAG_ELU) {
                const float cst = 0.9999950000374997f;
                float4 gv = *(const float4*)(eg + col);
                float4 ev = *(const float4*)(eb + col);
                v.x = v.x * cst * gv.x + ev.x;
                v.y = v.y * cst * gv.y + ev.y;
                v.z = v.z * cst * gv.z + ev.z;
                v.w = v.w * cst * gv.w + ev.w;
                v.x = v.x > 0.f ? v.x : expm1f(v.x);
                v.y = v.y > 0.f ? v.y : expm1f(v.y);
                v.z = v.z > 0.f ? v.z : expm1f(v.z);
                v.w = v.w > 0.f ? v.w : expm1f(v.w);
            }
            *(float4*)(C + row * N + col) = v;
        }
    }
}
#endif  // HAS_TCGEN05

__global__ __launch_bounds__(256, 1)
void sgemm_kernel(const float* __restrict__ A, const float* __restrict__ W,
                  const float* __restrict__ bias, const float* __restrict__ R,
                  const float* __restrict__ eg, const float* __restrict__ eb,
                  float* __restrict__ C, int N, int K, int flags, int Lc)
{
    gemm_tile(A, W, bias, R, eg, eb, C, N, K, flags, Lc,
              blockIdx.x, blockIdx.y);
}

__global__ __launch_bounds__(256, 1)
void qkv_kernel(const float* __restrict__ A,
                const float* __restrict__ wq, const float* __restrict__ wk,
                const float* __restrict__ wv,
                const float* __restrict__ bq, const float* __restrict__ bk,
                const float* __restrict__ bv,
                float* __restrict__ Qo, float* __restrict__ Ko,
                float* __restrict__ Vo, int K)
{
    int which = blockIdx.z;
    const float* W = which == 0 ? wq : (which == 1 ? wk : wv);
    const float* B = which == 0 ? bq : (which == 1 ? bk : bv);
    float*       C = which == 0 ? Qo : (which == 1 ? Ko : Vo);
    gemm_tile(A, W, B, nullptr, nullptr, nullptr, C, 512, K, FLAG_BIAS, 0,
              blockIdx.x, blockIdx.y);
}

// ------------------------- PE table + embedding -----------------------------
// one thread per (l, kk): double sincos on the same fp32 angle
__global__ void pe_kernel(float* __restrict__ PE)
{
    int i = blockIdx.x * blockDim.x + threadIdx.x;
    if (i >= LMAX * 256) return;
    int kk = i & 255;
    int l  = i >> 8;
    float prod = (float)(2 * kk) * -0.017988946039015984f;
    float divf = (float)exp((double)prod);
    float angf = (float)l * divf;
    double s, c;
    sincos((double)angf, &s, &c);
    float* row = PE + ((size_t)l << 9) + 2 * kk;
    row[0] = (float)s;
    row[1] = (float)c;
}

__global__ void embed_kernel(const float* __restrict__ xe,
                             const float* __restrict__ w,
                             const float* __restrict__ PE,
                             float* __restrict__ X)
{
    int i = blockIdx.x * blockDim.x + threadIdx.x;
    if (i >= BATCH * LMAX * D_MODEL) return;
    int d = i & 511;
    int l = (i >> 9) & (LMAX - 1);
    int b = i >> 20;
    float acc = 0.f;
    #pragma unroll
    for (int j = 0; j < 3; j++) {
        int ls = l + j - 1;
        if (ls < 0) ls += LMAX; else if (ls >= LMAX) ls -= LMAX;
        const float* xr = xe + ((size_t)b * LMAX + ls) * 2;
        acc += xr[0] * w[d * 6 + j] + xr[1] * w[d * 6 + 3 + j];
    }
    X[i] = acc + PE[i & (LMAX * D_MODEL - 1)];
}

// ------------------------- M = max_j(Q.K_idx) - sum_j(Q.K_idx)/L -------------
__global__ void msample_kernel(const float* __restrict__ Q,
                               const float* __restrict__ K,
                               const int* __restrict__ idx,
                               float* __restrict__ M, int L, int U)
{
    int w    = (blockIdx.x * blockDim.x + threadIdx.x) >> 5;
    int lane = threadIdx.x & 31;
    int total = NROW * L;
    if (w >= total) return;
    int l = w % L;
    int h = (w / L) % NH;
    int b = w / (L * NH);
    const float* qp = Q + ((size_t)b * L + l) * D_MODEL + h * DH;
    float q0 = qp[lane], q1 = qp[lane + 32];
    float mx = -3.4e38f, sm = 0.f;
    #pragma unroll 4
    for (int j = 0; j < U; j++) {
        int ki = idx[l * U + j];
        const float* kp = K + ((size_t)b * L + ki) * D_MODEL + h * DH;
        float p = q0 * kp[lane] + q1 * kp[lane + 32];
        #pragma unroll
        for (int o = 16; o > 0; o >>= 1) p += __shfl_xor_sync(0xffffffffu, p, o);
        mx = fmaxf(mx, p);
        sm += p;
    }
    if (lane == 0) M[((size_t)b * NH + h) * L + l] = mx - sm / (float)L;
}

// ------------------------- top-u selection (set semantics) ------------------
__global__ void topk_kernel(const float* __restrict__ M, int* __restrict__ top,
                            int L, int U)
{
    __shared__ float vals[LMAX];
    __shared__ unsigned char flags[LMAX];
    __shared__ float rv[256];
    __shared__ int   ri[256];
    int row = blockIdx.x;
    int t   = threadIdx.x;
    const float* mrow = M + (size_t)row * L;
    for (int l = t; l < L; l += 256) { vals[l] = mrow[l]; flags[l] = 0; }
    __syncthreads();
    for (int pass = 0; pass < U; pass++) {
        float bv = -3.4e38f; int bi = 0x7fffffff;
        for (int l = t; l < L; l += 256) {
            if (!flags[l]) {
                float v = vals[l];
                if (v > bv || (v == bv && l < bi)) { bv = v; bi = l; }
            }
        }
        rv[t] = bv; ri[t] = bi;
        __syncthreads();
        for (int s = 128; s > 0; s >>= 1) {
            if (t < s) {
                float ov = rv[t + s]; int oi = ri[t + s];
                if (ov > rv[t] || (ov == rv[t] && oi < ri[t])) { rv[t] = ov; ri[t] = oi; }
            }
            __syncthreads();
        }
        if (t == 0) { top[row * UMAX + pass] = ri[0]; flags[ri[0]] = 1; }
        __syncthreads();
    }
}

// ------------------------- V mean over L ------------------------------------
__global__ void vmean_kernel(const float* __restrict__ V, float* __restrict__ vm,
                             int L)
{
    __shared__ float red[256];
    int row = blockIdx.x;
    int b = row / NH, h = row % NH;
    int t = threadIdx.x;
    int e = t & 63, grp = t >> 6;
    float acc = 0.f;
    for (int l = grp; l < L; l += 4)
        acc += V[((size_t)b * L + l) * D_MODEL + h * DH + e];
    red[t] = acc;
    __syncthreads();
    if (t < 64)
        vm[(size_t)row * DH + t] =
            (red[t] + red[t + 64] + red[t + 128] + red[t + 192]) / (float)L;
}

__global__ void ofill_kernel(const float* __restrict__ vm, float* __restrict__ O,
                             int n, int L)
{
    int i = blockIdx.x * blockDim.x + threadIdx.x;
    if (i >= n) return;
    int d = i & 511;
    int b = i / (L * 512);
    O[i] = vm[(b * NH + (d >> 6)) * 64 + (d & 63)];
}

// ------------------------- flash-style attention ----------------------------
__global__ void attn_kernel(const float* __restrict__ Q,
                            const float* __restrict__ K,
                            const float* __restrict__ V,
                            const int* __restrict__ top,
                            float* __restrict__ PM, float* __restrict__ PS,
                            float* __restrict__ PA,
                            int L, int U, int keys)
{
    extern __shared__ float smf[];
    float* qs = smf;
    float* P  = qs + UMAX * APAD;
    float* Kt = P  + UMAX * APAD;
    float* Vt = Kt + 64 * APAD;
    __shared__ int qidx[UMAX];

    int split = blockIdx.x;
    int row   = blockIdx.y;
    int b = row / NH, h = row % NH;
    int t = threadIdx.x, lane = t & 31, w = t >> 5;

    if (t < U) qidx[t] = top[row * UMAX + t];
    __syncthreads();
    for (int p = t; p < U * 64; p += 256) {
        int j = p >> 6, e = p & 63;
        qs[j * APAD + e] = Q[((size_t)(b * L + qidx[j])) * D_MODEL + h * DH + e];
    }

    float m0[5], s0[5], a0[5], a1[5];
    #pragma unroll
    for (int r = 0; r < 5; r++) { m0[r] = -3.4e38f; s0[r] = 0.f; a0[r] = 0.f; a1[r] = 0.f; }
    __syncthreads();

    int base0 = split * keys;
    int ntile = keys >> 6;
    for (int tl = 0; tl < ntile; tl++) {
        int kb = base0 + (tl << 6);
        for (int i = t; i < 1024; i += 256) {
            int r = i >> 4, c = (i & 15) << 2;
            size_t gi = ((size_t)(b * L + kb + r)) * D_MODEL + h * DH + c;
            float4 kv = *(const float4*)(K + gi);
            float* dk = &Kt[r * APAD + c];
            dk[0] = kv.x; dk[1] = kv.y; dk[2] = kv.z; dk[3] = kv.w;
            float4 vv = *(const float4*)(V + gi);
            float* dv = &Vt[r * APAD + c];
            dv[0] = vv.x; dv[1] = vv.y; dv[2] = vv.z; dv[3] = vv.w;
        }
        __syncthreads();

        {
            float d0[5], d1[5];
            #pragma unroll
            for (int r = 0; r < 5; r++) { d0[r] = 0.f; d1[r] = 0.f; }
            const float* k0 = &Kt[lane * APAD];
            const float* k1 = &Kt[(lane + 32) * APAD];
            #pragma unroll 8
            for (int e = 0; e < 64; e++) {
                float ke0 = k0[e], ke1 = k1[e];
                #pragma unroll
                for (int r = 0; r < 5; r++) {
                    float qe = qs[(w + (r << 3)) * APAD + e];
                    d0[r] += qe * ke0;
                    d1[r] += qe * ke1;
                }
            }
            #pragma unroll
            for (int r = 0; r < 5; r++) {
                int j = w + (r << 3);
                if (j < U) {
                    P[j * APAD + lane]      = d0[r] * 0.125f;
                    P[j * APAD + lane + 32] = d1[r] * 0.125f;
                }
            }
        }
        __syncwarp();

        #pragma unroll
        for (int r = 0; r < 5; r++) {
            int j = w + (r << 3);
            if (j >= U) break;
            float v0 = P[j * APAD + lane], v1 = P[j * APAD + lane + 32];
            float tm = fmaxf(v0, v1);
            #pragma unroll
            for (int o = 16; o > 0; o >>= 1)
                tm = fmaxf(tm, __shfl_xor_sync(0xffffffffu, tm, o));
            float nm = fmaxf(m0[r], tm);
            float p0 = expf(v0 - nm), p1 = expf(v1 - nm);
            float ts = p0 + p1;
            #pragma unroll
            for (int o = 16; o > 0; o >>= 1)
                ts += __shfl_xor_sync(0xffffffffu, ts, o);
            float al = expf(m0[r] - nm);
            s0[r] = s0[r] * al + ts;
            a0[r] *= al; a1[r] *= al;
            m0[r] = nm;
            P[j * APAD + lane]      = p0;
            P[j * APAD + lane + 32] = p1;
        }
        __syncthreads();

        #pragma unroll 4
        for (int k = 0; k < 64; k++) {
            float ve0 = Vt[k * APAD + lane];
            float ve1 = Vt[k * APAD + lane + 32];
            #pragma unroll
            for (int r = 0; r < 5; r++) {
                float pk = P[(w + (r << 3)) * APAD + k];
                a0[r] += pk * ve0;
                a1[r] += pk * ve1;
            }
        }
        __syncthreads();
    }

    #pragma unroll
    for (int r = 0; r < 5; r++) {
        int j = w + (r << 3);
        if (j >= U) break;
        int pidx = (split * NROW + row) * UMAX + j;
        if (lane == 0) { PM[pidx] = m0[r]; PS[pidx] = s0[r]; }
        PA[(size_t)pidx * 64 + lane]      = a0[r];
        PA[(size_t)pidx * 64 + lane + 32] = a1[r];
    }
}

__global__ void attn_merge(const float* __restrict__ PM,
                           const float* __restrict__ PS,
                           const float* __restrict__ PA,
                           const int* __restrict__ top,
                           float* __restrict__ O, int L, int U, int nsplit)
{
    int gw = (blockIdx.x * blockDim.x + threadIdx.x) >> 5;
    int lane = threadIdx.x & 31;
    if (gw >= NROW * U) return;
    int row = gw / U, j = gw % U;
    int b = row / NH, h = row % NH;
    float M = -3.4e38f;
    for (int i = 0; i < nsplit; i++)
        M = fmaxf(M, PM[(i * NROW + row) * UMAX + j]);
    float s = 0.f, acc0 = 0.f, acc1 = 0.f;
    for (int i = 0; i < nsplit; i++) {
        int pidx = (i * NROW + row) * UMAX + j;
        float sc = expf(PM[pidx] - M);
        s    += PS[pidx] * sc;
        acc0 += PA[(size_t)pidx * 64 + lane] * sc;
        acc1 += PA[(size_t)pidx * 64 + lane + 32] * sc;
    }
    float inv = 1.f / s;
    int qi = top[row * UMAX + j];
    size_t o = ((size_t)(b * L + qi)) * D_MODEL + h * DH;
    O[o + lane]      = acc0 * inv;
    O[o + lane + 32] = acc1 * inv;
}

// ------------------------- LayerNorm (two-pass variance) --------------------
__global__ void ln_kernel(const float* __restrict__ X, const float* __restrict__ g,
                          const float* __restrict__ b, float* __restrict__ Y)
{
    __shared__ float s1[4], s2[4];
    int row = blockIdx.x, t = threadIdx.x;
    const float4 v = ((const float4*)(X + (size_t)row * D_MODEL))[t];
    float s = v.x + v.y + v.z + v.w;
    #pragma unroll
    for (int o = 16; o > 0; o >>= 1) s += __shfl_xor_sync(0xffffffffu, s, o);
    if ((t & 31) == 0) s1[t >> 5] = s;
    __syncthreads();
    float mean = (s1[0] + s1[1] + s1[2] + s1[3]) * (1.f / 512.f);
    float dx = v.x - mean, dy = v.y - mean, dz = v.z - mean, dw = v.w - mean;
    float ss = dx * dx + dy * dy + dz * dz + dw * dw;
    #pragma unroll
    for (int o = 16; o > 0; o >>= 1) ss += __shfl_xor_sync(0xffffffffu, ss, o);
    if ((t & 31) == 0) s2[t >> 5] = ss;
    __syncthreads();
    float var = (s2[0] + s2[1] + s2[2] + s2[3]) * (1.f / 512.f);
    float inv = 1.f / sqrtf(var + 1e-5f);
    const float4 g4 = ((const float4*)g)[t];
    const float4 b4 = ((const float4*)b)[t];
    float4 o;
    o.x = dx * inv * g4.x + b4.x;
    o.y = dy * inv * g4.y + b4.y;
    o.z = dz * inv * g4.z + b4.z;
    o.w = dw * inv * g4.w + b4.w;
    ((float4*)(Y + (size_t)row * D_MODEL))[t] = o;
}

// ------------------------- conv-distill helpers -----------------------------
// weight relayout: WC[n][j*512+c] = cv_w[n][c][j]
__global__ void wtrans_kernel(const float* __restrict__ cv, float* __restrict__ WC)
{
    int i = blockIdx.x * blockDim.x + threadIdx.x;
    if (i >= D_MODEL * 3 * D_MODEL) return;
    int n = i / 1536, k = i % 1536;
    int j = k / 512, c = k % 512;
    WC[i] = cv[(size_t)n * 1536 + c * 3 + j];
}

__global__ void pool_kernel(const float* __restrict__ Y, float* __restrict__ X,
                            int L)
{
    int Lh = L >> 1;
    int i = blockIdx.x * blockDim.x + threadIdx.x;
    if (i >= BATCH * Lh * 512) return;
    int d = i & 511;
    int m = (i >> 9) % Lh;
    int b = i / (Lh * 512);
    const float* yb = Y + (size_t)b * L * 512 + d;
    float v = fmaxf(yb[(size_t)(2 * m) * 512], yb[(size_t)(2 * m + 1) * 512]);
    if (m > 0) v = fmaxf(v, yb[(size_t)(2 * m - 1) * 512]);
    X[i] = v;
}

// ---------------------------------------------------------------------------
extern "C" void kernel_launch(void* const* d_in, const int* in_sizes, int n_in,
                              void* d_out, int out_size)
{
    (void)in_sizes; (void)n_in; (void)out_size;
    const float* x_enc = (const float*)d_in[0];
    const float* emb_w = (const float*)d_in[1];
    const float* Wq  = (const float*)d_in[2];
    const float* bq  = (const float*)d_in[3];
    const float* Wk  = (const float*)d_in[4];
    const float* bk  = (const float*)d_in[5];
    const float* Wv  = (const float*)d_in[6];
    const float* bv  = (const float*)d_in[7];
    const float* Wo  = (const float*)d_in[8];
    const float* bo  = (const float*)d_in[9];
    const float* ln1g = (const float*)d_in[10];
    const float* ln1b = (const float*)d_in[11];
    const float* W1  = (const float*)d_in[12];
    const float* b1  = (const float*)d_in[13];
    const float* W2  = (const float*)d_in[14];
    const float* b2  = (const float*)d_in[15];
    const float* ln2g = (const float*)d_in[16];
    const float* ln2b = (const float*)d_in[17];
    const float* cvw = (const float*)d_in[18];
    const float* cvb = (const float*)d_in[19];
    const float* bng = (const float*)d_in[20];
    const float* bnb = (const float*)d_in[21];
    const float* ngp = (const float*)d_in[22];
    const float* nbp = (const float*)d_in[23];

    float *X, *XN, *Yb, *Qb, *Kb, *Vb, *Ob, *H1b, *CVb, *WCb;
    float *PEb, *Mb, *VMb, *PMb, *PSb, *PAb;
    int *IDXb, *TOPb;
    cudaGetSymbolAddress((void**)&X,    g_X);
    cudaGetSymbolAddress((void**)&XN,   g_XN);
    cudaGetSymbolAddress((void**)&Yb,   g_Y);
    cudaGetSymbolAddress((void**)&Qb,   g_Q);
    cudaGetSymbolAddress((void**)&Kb,   g_K);
    cudaGetSymbolAddress((void**)&Vb,   g_V);
    cudaGetSymbolAddress((void**)&Ob,   g_O);
    cudaGetSymbolAddress((void**)&H1b,  g_H1);
    cudaGetSymbolAddress((void**)&CVb,  g_CV);
    cudaGetSymbolAddress((void**)&WCb,  g_WC);
    cudaGetSymbolAddress((void**)&PEb,  g_PE);
    cudaGetSymbolAddress((void**)&Mb,   g_M);
    cudaGetSymbolAddress((void**)&VMb,  g_VM);
    cudaGetSymbolAddress((void**)&PMb,  g_PM);
    cudaGetSymbolAddress((void**)&PSb,  g_PS);
    cudaGetSymbolAddress((void**)&PAb,  g_PA);
    cudaGetSymbolAddress((void**)&IDXb, g_IDX);
    cudaGetSymbolAddress((void**)&TOPb, g_TOP);

    const int attn_smem = (UMAX * APAD * 2 + 64 * APAD * 2) * 4;
    cudaFuncSetAttribute(attn_kernel,
                         cudaFuncAttributeMaxDynamicSharedMemorySize, attn_smem);
    cudaFuncSetAttribute(sgemm_kernel,
                         cudaFuncAttributeMaxDynamicSharedMemorySize, GEMM_SMEM);
    cudaFuncSetAttribute(qkv_kernel,
                         cudaFuncAttributeMaxDynamicSharedMemorySize, GEMM_SMEM);

    // launch order: pe(0), embed(1), idx0(2), qkv(3)... so the profiler's
    // fixed capture slot lands on the tcgen05 GEMM.
    pe_kernel<<<(LMAX * 256 + 255) / 256, 256>>>(PEb);
    {
        int total = BATCH * LMAX * D_MODEL;
        embed_kernel<<<(total + 255) / 256, 256>>>(x_enc, emb_w, PEb, X);
    }

    int Ls[3] = {2048, 1024, 512};
    int Us[3] = {40, 35, 35};
    // idx for layer 0 only (needed before layer-0 msample)
    {
        uint32_t f0, f1, k2a, k2b;
        threefry2x32(0u, 42u, 0u, 0u, &f0, &f1);
        threefry2x32(f0, f1, 0u, 1u, &k2a, &k2b);
        int nidx = Ls[0] * Us[0];
        idx_kernel<<<(nidx + 255) / 256, 256>>>(k2a, k2b, nidx,
                                                (unsigned)(Ls[0] - 1), IDXb);
    }

    int L = LMAX;
    for (int layer = 0; layer < 3; layer++) {
        int U = Us[layer];
        int Mrows = BATCH * L;
        dim3 gg(D_MODEL / 128, Mrows / 128);

        const float* wq = Wq + (size_t)layer * 512 * 512;
        const float* wk = Wk + (size_t)layer * 512 * 512;
        const float* wv = Wv + (size_t)layer * 512 * 512;
        const float* wo = Wo + (size_t)layer * 512 * 512;
        const float* w1 = W1 + (size_t)layer * 512 * 512;
        const float* w2 = W2 + (size_t)layer * 512 * 512;
        const int* idxp = IDXb + layer * LMAX * UMAX;

        {
            dim3 gq(D_MODEL / 128, Mrows / 128, 3);
            qkv_kernel<<<gq, 256, GEMM_SMEM>>>(X, wq, wk, wv,
                                               bq + layer * 512, bk + layer * 512,
                                               bv + layer * 512, Qb, Kb, Vb, 512);
        }

        // prefetch idx for the next layers (after layer-0 qkv)
        if (layer == 0) {
            for (int lay = 1; lay < 3; lay++) {
                uint32_t f0, f1, k2a, k2b;
                threefry2x32(0u, 42u, 0u, (uint32_t)lay, &f0, &f1);
                threefry2x32(f0, f1, 0u, 1u, &k2a, &k2b);
                int nidx = Ls[lay] * Us[lay];
                idx_kernel<<<(nidx + 255) / 256, 256>>>(
                    k2a, k2b, nidx, (unsigned)(Ls[lay] - 1),
                    IDXb + lay * LMAX * UMAX);
            }
        }

        int warps = NROW * L;
        msample_kernel<<<(warps * 32 + 255) / 256, 256>>>(Qb, Kb, idxp, Mb, L, U);
        topk_kernel<<<NROW, 256>>>(Mb, TOPb, L, U);
        vmean_kernel<<<NROW, 256>>>(Vb, VMb, L);
        ofill_kernel<<<(Mrows * 512 + 255) / 256, 256>>>(VMb, Ob, Mrows * 512, L);

        {
            int keys = 512;
            int nsplit = L / keys;
            dim3 ag(nsplit, NROW);
            attn_kernel<<<ag, 256, attn_smem>>>(Qb, Kb, Vb, TOPb,
                                                PMb, PSb, PAb, L, U, keys);
            int mw = NROW * U;
            attn_merge<<<(mw * 32 + 255) / 256, 256>>>(PMb, PSb, PAb, TOPb,
                                                       Ob, L, U, nsplit);
        }

        sgemm_kernel<<<gg, 256, GEMM_SMEM>>>(Ob, wo, bo + layer * 512, X,
                                             nullptr, nullptr, Yb, 512, 512,
                                             FLAG_BIAS | FLAG_RES, 0);
        ln_kernel<<<Mrows, 128>>>(Yb, ln1g + layer * 512, ln1b + layer * 512, XN);
        sgemm_kernel<<<gg, 256, GEMM_SMEM>>>(XN, w1, b1 + layer * 512, nullptr,
                                             nullptr, nullptr, H1b, 512, 512,
                                             FLAG_BIAS | FLAG_GELU, 0);
        sgemm_kernel<<<gg, 256, GEMM_SMEM>>>(H1b, w2, b2 + layer * 512, XN,
                                             nullptr, nullptr, Yb, 512, 512,
                                             FLAG_BIAS | FLAG_RES, 0);
        ln_kernel<<<Mrows, 128>>>(Yb, ln2g + layer * 512, ln2b + layer * 512, X);

        if (layer < 2) {
            wtrans_kernel<<<(512 * 1536 + 255) / 256, 256>>>(
                cvw + (size_t)layer * 512 * 1536, WCb);
            sgemm_kernel<<<gg, 256, GEMM_SMEM>>>(X, WCb, cvb + layer * 512,
                                                 nullptr, bng + layer * 512,
                                                 bnb + layer * 512, CVb, 512, 1536,
                                                 FLAG_BIAS | FLAG_ELU | FLAG_CIRC, L);
            int Lh = L / 2;
            pool_kernel<<<(BATCH * Lh * 512 + 255) / 256, 256>>>(CVb, X, L);
            L = Lh;
        }
    }

    ln_kernel<<<BATCH * L, 128>>>(X, ngp, nbp, (float*)d_out);
}

// round 17
// speedup vs baseline: 1.2942x; 1.0450x over previous
#include <cuda_runtime.h>
#include <stdint.h>
#include <math.h>

// ---------------------------------------------------------------------------
// InformerEncoder: B=4, L0=2048, C=2, D=512, F=512, H=8, dh=64, EL=3
// Numerics: exact-fp32 model via 3xTF32 (hi/lo split in-kernel), tcgen05 on
// the sm_103a cubin; scalar fallback for the generic sm_103 PTX pass.
// GEMM: DOUBLE-buffered smem (129KB, 1 CTA/SM), 512 threads (16 warps) so the
// producer hides global-load latency; producer of chunk c+1 overlaps the
// async mma of chunk c. Alloc permit relinquished at END (R13/R14 evidence).
// ---------------------------------------------------------------------------
#define D_MODEL 512
#define BATCH   4
#define LMAX    2048
#define NH      8
#define DH      64
#define UMAX    40
#define NROW    (BATCH*NH)
#define APAD    65

#define FLAG_BIAS 1
#define FLAG_RES  2
#define FLAG_GELU 4
#define FLAG_ELU  8
#define FLAG_CIRC 16

#define GEMM_CHUNK 32
#define GEMM_THREADS 512
#define TILE_B     16384                 // one 128x32 fp32 tile in bytes
#define GEMM_SMEM  (1024 + 8*TILE_B)     // align slack + 2 bufs x 4 tiles
// idesc: dtype f32 | atype tf32 | btype tf32 | N=128 | M=128
#define TC_IDESC ((1u<<4)|(2u<<7)|(2u<<10)|((128u/8)<<17)|((128u/16)<<24))

#if defined(__CUDA_ARCH_FEAT_SM103_ALL)
#define HAS_TCGEN05 1
#else
#define HAS_TCGEN05 0
#endif

// ------------------------- scratch (static device globals) ------------------
__device__ float g_X   [BATCH*LMAX*D_MODEL];
__device__ float g_XN  [BATCH*LMAX*D_MODEL];
__device__ float g_Y   [BATCH*LMAX*D_MODEL];
__device__ float g_Q   [BATCH*LMAX*D_MODEL];
__device__ float g_K   [BATCH*LMAX*D_MODEL];
__device__ float g_V   [BATCH*LMAX*D_MODEL];
__device__ float g_O   [BATCH*LMAX*D_MODEL];
__device__ float g_H1  [BATCH*LMAX*D_MODEL];
__device__ float g_CV  [BATCH*LMAX*D_MODEL];
__device__ float g_WC  [D_MODEL*3*D_MODEL];
__device__ float g_PE  [LMAX*D_MODEL];
__device__ int   g_IDX [3*LMAX*UMAX];
__device__ float g_M   [NROW*LMAX];
__device__ int   g_TOP [NROW*UMAX];
__device__ float g_VM  [NROW*DH];
__device__ float g_PM  [4*NROW*UMAX];
__device__ float g_PS  [4*NROW*UMAX];
__device__ float g_PA  [4*NROW*UMAX*DH];

// ------------------------- threefry2x32 (JAX-compatible) --------------------
__host__ __device__ inline void threefry2x32(uint32_t k0, uint32_t k1,
                                             uint32_t x0, uint32_t x1,
                                             uint32_t* o0, uint32_t* o1)
{
    uint32_t ks0 = k0, ks1 = k1, ks2 = k0 ^ k1 ^ 0x1BD11BDAu;
    uint32_t ks[3] = {ks0, ks1, ks2};
    x0 += ks0; x1 += ks1;
    const int rA[4] = {13, 15, 26, 6};
    const int rB[4] = {17, 29, 16, 24};
    #pragma unroll
    for (int g = 0; g < 5; ++g) {
        const int* r = (g & 1) ? rB : rA;
        #pragma unroll
        for (int i = 0; i < 4; ++i) {
            x0 += x1;
            x1 = (x1 << r[i]) | (x1 >> (32 - r[i]));
            x1 ^= x0;
        }
        x0 += ks[(g + 1) % 3];
        x1 += ks[(g + 2) % 3] + (uint32_t)(g + 1);
    }
    *o0 = x0; *o1 = x1;
}

__global__ void idx_kernel(uint32_t k0, uint32_t k1, int n, unsigned mask,
                           int* __restrict__ idx)
{
    int j = blockIdx.x * blockDim.x + threadIdx.x;
    if (j >= n) return;
    uint32_t o0, o1;
    threefry2x32(k0, k1, 0u, (uint32_t)j, &o0, &o1);
    idx[j] = (int)((o0 ^ o1) & mask);
}

// ------------------------- common helpers -----------------------------------
__device__ __forceinline__ float gelu_exact(float x)
{
    return 0.5f * x * (1.0f + erff(x * 0.70710678118654752f));
}

__device__ __forceinline__ float tf32f(float x)
{
    uint32_t u;
    asm("cvt.rna.tf32.f32 %0, %1;" : "=r"(u) : "f"(x));
    return __uint_as_float(u);
}

__device__ __forceinline__ void split4(float4 v, float4* h, float4* l)
{
    h->x = tf32f(v.x); l->x = tf32f(v.x - h->x);
    h->y = tf32f(v.y); l->y = tf32f(v.y - h->y);
    h->z = tf32f(v.z); l->z = tf32f(v.z - h->z);
    h->w = tf32f(v.w); l->w = tf32f(v.w - h->w);
}

#if HAS_TCGEN05
// ===================== tcgen05 backend (sm_103a target) =====================
__device__ __forceinline__ uint32_t s2u(const void* p)
{
    uint32_t a;
    asm("{ .reg .u64 t; cvta.to.shared.u64 t, %1; cvt.u32.u64 %0, t; }"
        : "=r"(a) : "l"(p));
    return a;
}

__device__ __forceinline__ uint64_t sdesc(uint32_t a)
{
    return (2ULL << 61) | (1ULL << 46) | (64ULL << 32) | (1ULL << 16)
         | (uint64_t)((a >> 4) & 0x3FFF);
}

__device__ __forceinline__ uint32_t swz(uint32_t b)
{
    return b ^ ((b >> 3) & 0x70);
}

__device__ __forceinline__ void tcmma_tf32(uint32_t d, uint64_t a, uint64_t b,
                                           uint32_t idesc, uint32_t en)
{
    asm volatile(
        "{\n\t"
        ".reg .pred p;\n\t"
        "setp.ne.u32 p, %5, 0;\n\t"
        "tcgen05.mma.cta_group::1.kind::tf32 [%0], %1, %2, %3, {%4,%4,%4,%4}, p;\n\t"
        "}"
        :: "r"(d), "l"(a), "l"(b), "r"(idesc), "r"(0u), "r"(en)
        : "memory");
}

__device__ __forceinline__ void tc_commit(uint32_t mbar)
{
    asm volatile(
        "tcgen05.commit.cta_group::1.mbarrier::arrive::one.shared::cluster.b64 [%0];"
        :: "r"(mbar) : "memory");
}

__device__ __forceinline__ void mbar_wait(uint32_t mbar, uint32_t parity)
{
    asm volatile(
        "{\n\t"
        ".reg .pred P;\n\t"
        "W_%=:\n\t"
        "mbarrier.try_wait.parity.shared.b64 P, [%0], %1;\n\t"
        "@!P bra W_%=;\n\t"
        "}"
        :: "r"(mbar), "r"(parity) : "memory");
}

#define TC_LD_X32(r, addr) \
    asm volatile( \
        "tcgen05.ld.sync.aligned.32x32b.x32.b32 " \
        "{%0, %1, %2, %3, %4, %5, %6, %7, " \
        " %8, %9, %10, %11, %12, %13, %14, %15, " \
        " %16, %17, %18, %19, %20, %21, %22, %23, " \
        " %24, %25, %26, %27, %28, %29, %30, %31}, [%32];" \
        : "=r"((r)[0]),  "=r"((r)[1]),  "=r"((r)[2]),  "=r"((r)[3]), \
          "=r"((r)[4]),  "=r"((r)[5]),  "=r"((r)[6]),  "=r"((r)[7]), \
          "=r"((r)[8]),  "=r"((r)[9]),  "=r"((r)[10]), "=r"((r)[11]), \
          "=r"((r)[12]), "=r"((r)[13]), "=r"((r)[14]), "=r"((r)[15]), \
          "=r"((r)[16]), "=r"((r)[17]), "=r"((r)[18]), "=r"((r)[19]), \
          "=r"((r)[20]), "=r"((r)[21]), "=r"((r)[22]), "=r"((r)[23]), \
          "=r"((r)[24]), "=r"((r)[25]), "=r"((r)[26]), "=r"((r)[27]), \
          "=r"((r)[28]), "=r"((r)[29]), "=r"((r)[30]), "=r"((r)[31]) \
        : "r"(addr))

// C = A @ W^T, 3xTF32 (hi/lo split in producer). 128x128 tile, DOUBLE buffer,
// 512 threads: producer of chunk c+1 overlaps the async mma of chunk c.
// FLAG_CIRC: A read from X[B,Lc,512] with circular row offset j-1 (j = k/512).
__device__ __forceinline__ void gemm_tile(
    const float* __restrict__ A, const float* __restrict__ W,
    const float* __restrict__ bias, const float* __restrict__ R,
    const float* __restrict__ eg, const float* __restrict__ eb,
    float* __restrict__ C, int N, int K, int flags, int Lc, int bx, int by)
{
    extern __shared__ char dsm[];
    __shared__ uint32_t s_tmem[1];
    __shared__ uint64_t s_mbar[2];

    const int t = threadIdx.x;
    const uint32_t daddr = s2u(dsm);
    const uint32_t aoff  = (1024u - (daddr & 1023u)) & 1023u;
    char* tb = dsm + aoff;
    const uint32_t tb_addr = daddr + aoff;

    const uint32_t ctrl = s2u(s_tmem);
    const uint32_t mb0  = s2u(&s_mbar[0]);
    const uint32_t mb1  = s2u(&s_mbar[1]);

    if (t < 32)
        asm volatile(
            "tcgen05.alloc.cta_group::1.sync.aligned.shared::cta.b32 [%0], %1;"
            :: "r"(ctrl), "r"(128u) : "memory");
    if (t == 0) {
        asm volatile("mbarrier.init.shared.b64 [%0], 1;" :: "r"(mb0) : "memory");
        asm volatile("mbarrier.init.shared.b64 [%0], 1;" :: "r"(mb1) : "memory");
    }
    __syncthreads();
    const uint32_t tmem_base = s_tmem[0];

    const float* Ab  = A + (size_t)by * 128 * K;   // non-circ path
    const float* Wb  = W + (size_t)bx * 128 * K;
    const int growb  = by * 128;

    const int nb = K / GEMM_CHUNK;
    int ph0 = 0, ph1 = 0;

    for (int c = 0; c < nb; c++) {
        const int buf = c & 1;
        if (c >= 2) {
            if (buf == 0) { mbar_wait(mb0, (uint32_t)(ph0 & 1)); ph0++; }
            else          { mbar_wait(mb1, (uint32_t)(ph1 & 1)); ph1++; }
        }
        const int cbase = c * GEMM_CHUNK;
        char* bufp = tb + buf * (4 * TILE_B);
        #pragma unroll
        for (int i = 0; i < 2; i++) {
            const int idx = t + i * GEMM_THREADS;  // 0..1023
            const int row = idx >> 3, c4 = idx & 7;
            const uint32_t off = swz((uint32_t)(row * 128 + c4 * 16));
            float4 av;
            if (flags & FLAG_CIRC) {
                const int grow = growb + row;
                const int bb = grow / Lc, l = grow - bb * Lc;
                const int j = cbase >> 9;          // kernel tap 0..2
                int sr = l + j - 1;
                if (sr < 0) sr += Lc; else if (sr >= Lc) sr -= Lc;
                av = *(const float4*)(A + ((size_t)(bb * Lc + sr)) * 512
                                        + (cbase & 511) + c4 * 4);
            } else {
                av = *(const float4*)(Ab + (size_t)row * K + cbase + c4 * 4);
            }
            const float4 wv = *(const float4*)(Wb + (size_t)row * K + cbase + c4 * 4);
            float4 h, l4;
            split4(av, &h, &l4);
            *(float4*)(bufp + off)              = h;
            *(float4*)(bufp + TILE_B + off)     = l4;
            split4(wv, &h, &l4);
            *(float4*)(bufp + 2 * TILE_B + off) = h;
            *(float4*)(bufp + 3 * TILE_B + off) = l4;
        }
        asm volatile("fence.proxy.async.shared::cta;" ::: "memory");
        __syncthreads();
        if (t == 0) {
            const uint32_t ba = tb_addr + buf * (4 * TILE_B);
            const uint64_t dah = sdesc(ba);
            const uint64_t dal = sdesc(ba + TILE_B);
            const uint64_t dwh = sdesc(ba + 2 * TILE_B);
            const uint64_t dwl = sdesc(ba + 3 * TILE_B);
            #pragma unroll
            for (int s = 0; s < 4; s++) {
                const uint32_t en0 = (c == 0 && s == 0) ? 0u : 1u;
                tcmma_tf32(tmem_base, dah + s * 2, dwl + s * 2, TC_IDESC, en0);
                tcmma_tf32(tmem_base, dal + s * 2, dwh + s * 2, TC_IDESC, 1u);
                tcmma_tf32(tmem_base, dah + s * 2, dwh + s * 2, TC_IDESC, 1u);
            }
            tc_commit(buf ? mb1 : mb0);
        }
        // no wait here: producer for chunk c+1 overlaps mma of chunk c
    }

    mbar_wait(mb0, (uint32_t)(ph0 & 1));
    if (nb >= 2) mbar_wait(mb1, (uint32_t)(ph1 & 1));
    asm volatile("tcgen05.fence::after_thread_sync;" ::: "memory");

    // epilogue: 16 warps; warp w covers rows (w&3)*32+lane (subpartition is
    // implicit via warp%4) and 32 cols at (w>>2)*32. One LDTM burst each.
    const int w = t >> 5, lane = t & 31;
    const int rown = (w & 3) * 32 + lane;
    const int colw = (w >> 2) * 32;
    const size_t grow = (size_t)(by * 128 + rown);

    {
        uint32_t dr[32];
        TC_LD_X32(dr, tmem_base + colw);
        asm volatile("tcgen05.wait::ld.sync.aligned;" ::: "memory");
        const int cb = bx * 128 + colw;
        float* crow = C + grow * N + cb;
        const float* rrow = (flags & FLAG_RES) ? (R + grow * N + cb) : nullptr;
        #pragma unroll
        for (int q = 0; q < 8; q++) {
            float v0 = __uint_as_float(dr[q * 4 + 0]);
            float v1 = __uint_as_float(dr[q * 4 + 1]);
            float v2 = __uint_as_float(dr[q * 4 + 2]);
            float v3 = __uint_as_float(dr[q * 4 + 3]);
            if (flags & FLAG_BIAS) {
                float4 bz = *(const float4*)(bias + cb + q * 4);
                v0 += bz.x; v1 += bz.y; v2 += bz.z; v3 += bz.w;
            }
            if (flags & FLAG_RES) {
                float4 rr = *(const float4*)(rrow + q * 4);
                v0 += rr.x; v1 += rr.y; v2 += rr.z; v3 += rr.w;
            }
            if (flags & FLAG_GELU) {
                v0 = gelu_exact(v0); v1 = gelu_exact(v1);
                v2 = gelu_exact(v2); v3 = gelu_exact(v3);
            }
            if (flags & FLAG_ELU) {
                const float cst = 0.9999950000374997f;   // 1/sqrt(1+1e-5)
                float4 gv = *(const float4*)(eg + cb + q * 4);
                float4 ev = *(const float4*)(eb + cb + q * 4);
                v0 = v0 * cst * gv.x + ev.x;
                v1 = v1 * cst * gv.y + ev.y;
                v2 = v2 * cst * gv.z + ev.z;
                v3 = v3 * cst * gv.w + ev.w;
                v0 = v0 > 0.f ? v0 : expm1f(v0);
                v1 = v1 > 0.f ? v1 : expm1f(v1);
                v2 = v2 > 0.f ? v2 : expm1f(v2);
                v3 = v3 > 0.f ? v3 : expm1f(v3);
            }
            *(float4*)(crow + q * 4) = make_float4(v0, v1, v2, v3);
        }
    }

    __syncthreads();
    if (t == 0) {
        asm volatile("mbarrier.inval.shared.b64 [%0];" :: "r"(mb0) : "memory");
        asm volatile("mbarrier.inval.shared.b64 [%0];" :: "r"(mb1) : "memory");
    }
    if (t < 32) {
        asm volatile("tcgen05.relinquish_alloc_permit.cta_group::1.sync.aligned;");
        asm volatile("tcgen05.dealloc.cta_group::1.sync.aligned.b32 %0, %1;"
                     :: "r"(tmem_base), "r"(128u));
    }
}

#else
// ============ scalar fallback (generic sm_103 PTX pass; never runs) =========
__device__ __forceinline__ void gemm_tile(
    const float* __restrict__ A, const float* __restrict__ W,
    const float* __restrict__ bias, const float* __restrict__ R,
    const float* __restrict__ eg, const float* __restrict__ eb,
    float* __restrict__ C, int N, int K, int flags, int Lc, int bx, int by)
{
    extern __shared__ char dsm[];
    float* As = (float*)dsm;             // [8][128]
    float* Ws = As + 8 * 128;            // [8][128]
    const int t    = threadIdx.x;
    const int act  = (t < 256);
    const int tx   = t & 15;
    const int ty   = (t >> 4) & 15;
    const int lrow = (t >> 1) & 127;
    const int lseg = (t & 1) << 2;

    const float* Ab = A + (size_t)by * 128 * K;
    const float* Wb = W + (size_t)bx * 128 * K;

    float acc[8][8];
    #pragma unroll
    for (int i = 0; i < 8; i++)
        #pragma unroll
        for (int j = 0; j < 8; j++) acc[i][j] = 0.f;

    for (int k0 = 0; k0 < K; k0 += 8) {
        if (act) {
            float4 a4;
            if (flags & FLAG_CIRC) {
                const int grow = by * 128 + lrow;
                const int bb = grow / Lc, l = grow - bb * Lc;
                const int kk = k0 + lseg;
                const int j = kk >> 9;
                int sr = l + j - 1;
                if (sr < 0) sr += Lc; else if (sr >= Lc) sr -= Lc;
                a4 = *(const float4*)(A + ((size_t)(bb * Lc + sr)) * 512 + (kk & 511));
            } else {
                a4 = *(const float4*)(Ab + (size_t)lrow * K + k0 + lseg);
            }
            float4 w4 = *(const float4*)(Wb + (size_t)lrow * K + k0 + lseg);
            As[(lseg + 0) * 128 + lrow] = a4.x;
            As[(lseg + 1) * 128 + lrow] = a4.y;
            As[(lseg + 2) * 128 + lrow] = a4.z;
            As[(lseg + 3) * 128 + lrow] = a4.w;
            Ws[(lseg + 0) * 128 + lrow] = w4.x;
            Ws[(lseg + 1) * 128 + lrow] = w4.y;
            Ws[(lseg + 2) * 128 + lrow] = w4.z;
            Ws[(lseg + 3) * 128 + lrow] = w4.w;
        }
        __syncthreads();
        if (act) {
            #pragma unroll
            for (int k = 0; k < 8; k++) {
                float av[8], bv[8];
                #pragma unroll
                for (int i = 0; i < 8; i++) av[i] = As[k * 128 + ty * 8 + i];
                #pragma unroll
                for (int j = 0; j < 8; j++) bv[j] = Ws[k * 128 + tx * 8 + j];
                #pragma unroll
                for (int i = 0; i < 8; i++)
                    #pragma unroll
                    for (int j = 0; j < 8; j++)
                        acc[i][j] += av[i] * bv[j];
            }
        }
        __syncthreads();
    }

    if (act) {
        const int colbase = bx * 128 + tx * 8;
        #pragma unroll
        for (int i = 0; i < 8; i++) {
            size_t row = (size_t)by * 128 + ty * 8 + i;
            #pragma unroll
            for (int jq = 0; jq < 2; jq++) {
                float4 v;
                v.x = acc[i][jq * 4 + 0]; v.y = acc[i][jq * 4 + 1];
                v.z = acc[i][jq * 4 + 2]; v.w = acc[i][jq * 4 + 3];
                const int col = colbase + jq * 4;
                if (flags & FLAG_BIAS) {
                    float4 bz = *(const float4*)(bias + col);
                    v.x += bz.x; v.y += bz.y; v.z += bz.z; v.w += bz.w;
                }
                if (flags & FLAG_RES) {
                    float4 rr = *(const float4*)(R + row * N + col);
                    v.x += rr.x; v.y += rr.y; v.z += rr.z; v.w += rr.w;
                }
                if (flags & FLAG_GELU) {
                    v.x = gelu_exact(v.x); v.y = gelu_exact(v.y);
                    v.z = gelu_exact(v.z); v.w = gelu_exact(v.w);
                }
                if (flags & FLAG_ELU) {
                    const float cst = 0.9999950000374997f;
                    float4 gv = *(const float4*)(eg + col);
                    float4 ev = *(const float4*)(eb + col);
                    v.x = v.x * cst * gv.x + ev.x;
                    v.y = v.y * cst * gv.y + ev.y;
                    v.z = v.z * cst * gv.z + ev.z;
                    v.w = v.w * cst * gv.w + ev.w;
                    v.x = v.x > 0.f ? v.x : expm1f(v.x);
                    v.y = v.y > 0.f ? v.y : expm1f(v.y);
                    v.z = v.z > 0.f ? v.z : expm1f(v.z);
                    v.w = v.w > 0.f ? v.w : expm1f(v.w);
                }
                *(float4*)(C + row * N + col) = v;
            }
        }
    }
}
#endif  // HAS_TCGEN05

__global__ __launch_bounds__(GEMM_THREADS, 1)
void sgemm_kernel(const float* __restrict__ A, const float* __restrict__ W,
                  const float* __restrict__ bias, const float* __restrict__ R,
                  const float* __restrict__ eg, const float* __restrict__ eb,
                  float* __restrict__ C, int N, int K, int flags, int Lc)
{
    gemm_tile(A, W, bias, R, eg, eb, C, N, K, flags, Lc,
              blockIdx.x, blockIdx.y);
}

__global__ __launch_bounds__(GEMM_THREADS, 1)
void qkv_kernel(const float* __restrict__ A,
                const float* __restrict__ wq, const float* __restrict__ wk,
                const float* __restrict__ wv,
                const float* __restrict__ bq, const float* __restrict__ bk,
                const float* __restrict__ bv,
                float* __restrict__ Qo, float* __restrict__ Ko,
                float* __restrict__ Vo, int K)
{
    int which = blockIdx.z;
    const float* W = which == 0 ? wq : (which == 1 ? wk : wv);
    const float* B = which == 0 ? bq : (which == 1 ? bk : bv);
    float*       C = which == 0 ? Qo : (which == 1 ? Ko : Vo);
    gemm_tile(A, W, B, nullptr, nullptr, nullptr, C, 512, K, FLAG_BIAS, 0,
              blockIdx.x, blockIdx.y);
}

// ------------------------- PE table + embedding -----------------------------
// one thread per (l, kk): double sincos on the same fp32 angle
__global__ void pe_kernel(float* __restrict__ PE)
{
    int i = blockIdx.x * blockDim.x + threadIdx.x;
    if (i >= LMAX * 256) return;
    int kk = i & 255;
    int l  = i >> 8;
    float prod = (float)(2 * kk) * -0.017988946039015984f;
    float divf = (float)exp((double)prod);
    float angf = (float)l * divf;
    double s, c;
    sincos((double)angf, &s, &c);
    float* row = PE + ((size_t)l << 9) + 2 * kk;
    row[0] = (float)s;
    row[1] = (float)c;
}

__global__ void embed_kernel(const float* __restrict__ xe,
                             const float* __restrict__ w,
                             const float* __restrict__ PE,
                             float* __restrict__ X)
{
    int i = blockIdx.x * blockDim.x + threadIdx.x;
    if (i >= BATCH * LMAX * D_MODEL) return;
    int d = i & 511;
    int l = (i >> 9) & (LMAX - 1);
    int b = i >> 20;
    float acc = 0.f;
    #pragma unroll
    for (int j = 0; j < 3; j++) {
        int ls = l + j - 1;
        if (ls < 0) ls += LMAX; else if (ls >= LMAX) ls -= LMAX;
        const float* xr = xe + ((size_t)b * LMAX + ls) * 2;
        acc += xr[0] * w[d * 6 + j] + xr[1] * w[d * 6 + 3 + j];
    }
    X[i] = acc + PE[i & (LMAX * D_MODEL - 1)];
}

// ------------------------- M = max_j(Q.K_idx) - sum_j(Q.K_idx)/L -------------
__global__ void msample_kernel(const float* __restrict__ Q,
                               const float* __restrict__ K,
                               const int* __restrict__ idx,
                               float* __restrict__ M, int L, int U)
{
    int w    = (blockIdx.x * blockDim.x + threadIdx.x) >> 5;
    int lane = threadIdx.x & 31;
    int total = NROW * L;
    if (w >= total) return;
    int l = w % L;
    int h = (w / L) % NH;
    int b = w / (L * NH);
    const float* qp = Q + ((size_t)b * L + l) * D_MODEL + h * DH;
    float q0 = qp[lane], q1 = qp[lane + 32];
    float mx = -3.4e38f, sm = 0.f;
    #pragma unroll 4
    for (int j = 0; j < U; j++) {
        int ki = idx[l * U + j];
        const float* kp = K + ((size_t)b * L + ki) * D_MODEL + h * DH;
        float p = q0 * kp[lane] + q1 * kp[lane + 32];
        #pragma unroll
        for (int o = 16; o > 0; o >>= 1) p += __shfl_xor_sync(0xffffffffu, p, o);
        mx = fmaxf(mx, p);
        sm += p;
    }
    if (lane == 0) M[((size_t)b * NH + h) * L + l] = mx - sm / (float)L;
}

// ------------------------- top-u selection (set semantics) ------------------
__global__ void topk_kernel(const float* __restrict__ M, int* __restrict__ top,
                            int L, int U)
{
    __shared__ float vals[LMAX];
    __shared__ unsigned char flags[LMAX];
    __shared__ float rv[256];
    __shared__ int   ri[256];
    int row = blockIdx.x;
    int t   = threadIdx.x;
    const float* mrow = M + (size_t)row * L;
    for (int l = t; l < L; l += 256) { vals[l] = mrow[l]; flags[l] = 0; }
    __syncthreads();
    for (int pass = 0; pass < U; pass++) {
        float bv = -3.4e38f; int bi = 0x7fffffff;
        for (int l = t; l < L; l += 256) {
            if (!flags[l]) {
                float v = vals[l];
                if (v > bv || (v == bv && l < bi)) { bv = v; bi = l; }
            }
        }
        rv[t] = bv; ri[t] = bi;
        __syncthreads();
        for (int s = 128; s > 0; s >>= 1) {
            if (t < s) {
                float ov = rv[t + s]; int oi = ri[t + s];
                if (ov > rv[t] || (ov == rv[t] && oi < ri[t])) { rv[t] = ov; ri[t] = oi; }
            }
            __syncthreads();
        }
        if (t == 0) { top[row * UMAX + pass] = ri[0]; flags[ri[0]] = 1; }
        __syncthreads();
    }
}

// ------------------------- V mean over L ------------------------------------
__global__ void vmean_kernel(const float* __restrict__ V, float* __restrict__ vm,
                             int L)
{
    __shared__ float red[256];
    int row = blockIdx.x;
    int b = row / NH, h = row % NH;
    int t = threadIdx.x;
    int e = t & 63, grp = t >> 6;
    float acc = 0.f;
    for (int l = grp; l < L; l += 4)
        acc += V[((size_t)b * L + l) * D_MODEL + h * DH + e];
    red[t] = acc;
    __syncthreads();
    if (t < 64)
        vm[(size_t)row * DH + t] =
            (red[t] + red[t + 64] + red[t + 128] + red[t + 192]) / (float)L;
}

__global__ void ofill_kernel(const float* __restrict__ vm, float* __restrict__ O,
                             int n, int L)
{
    int i = blockIdx.x * blockDim.x + threadIdx.x;
    if (i >= n) return;
    int d = i & 511;
    int b = i / (L * 512);
    O[i] = vm[(b * NH + (d >> 6)) * 64 + (d & 63)];
}

// ------------------------- flash-style attention ----------------------------
__global__ void attn_kernel(const float* __restrict__ Q,
                            const float* __restrict__ K,
                            const float* __restrict__ V,
                            const int* __restrict__ top,
                            float* __restrict__ PM, float* __restrict__ PS,
                            float* __restrict__ PA,
                            int L, int U, int keys)
{
    extern __shared__ float smf[];
    float* qs = smf;
    float* P  = qs + UMAX * APAD;
    float* Kt = P  + UMAX * APAD;
    float* Vt = Kt + 64 * APAD;
    __shared__ int qidx[UMAX];

    int split = blockIdx.x;
    int row   = blockIdx.y;
    int b = row / NH, h = row % NH;
    int t = threadIdx.x, lane = t & 31, w = t >> 5;

    if (t < U) qidx[t] = top[row * UMAX + t];
    __syncthreads();
    for (int p = t; p < U * 64; p += 256) {
        int j = p >> 6, e = p & 63;
        qs[j * APAD + e] = Q[((size_t)(b * L + qidx[j])) * D_MODEL + h * DH + e];
    }

    float m0[5], s0[5], a0[5], a1[5];
    #pragma unroll
    for (int r = 0; r < 5; r++) { m0[r] = -3.4e38f; s0[r] = 0.f; a0[r] = 0.f; a1[r] = 0.f; }
    __syncthreads();

    int base0 = split * keys;
    int ntile = keys >> 6;
    for (int tl = 0; tl < ntile; tl++) {
        int kb = base0 + (tl << 6);
        for (int i = t; i < 1024; i += 256) {
            int r = i >> 4, c = (i & 15) << 2;
            size_t gi = ((size_t)(b * L + kb + r)) * D_MODEL + h * DH + c;
            float4 kv = *(const float4*)(K + gi);
            float* dk = &Kt[r * APAD + c];
            dk[0] = kv.x; dk[1] = kv.y; dk[2] = kv.z; dk[3] = kv.w;
            float4 vv = *(const float4*)(V + gi);
            float* dv = &Vt[r * APAD + c];
            dv[0] = vv.x; dv[1] = vv.y; dv[2] = vv.z; dv[3] = vv.w;
        }
        __syncthreads();

        {
            float d0[5], d1[5];
            #pragma unroll
            for (int r = 0; r < 5; r++) { d0[r] = 0.f; d1[r] = 0.f; }
            const float* k0 = &Kt[lane * APAD];
            const float* k1 = &Kt[(lane + 32) * APAD];
            #pragma unroll 8
            for (int e = 0; e < 64; e++) {
                float ke0 = k0[e], ke1 = k1[e];
                #pragma unroll
                for (int r = 0; r < 5; r++) {
                    float qe = qs[(w + (r << 3)) * APAD + e];
                    d0[r] += qe * ke0;
                    d1[r] += qe * ke1;
                }
            }
            #pragma unroll
            for (int r = 0; r < 5; r++) {
                int j = w + (r << 3);
                if (j < U) {
                    P[j * APAD + lane]      = d0[r] * 0.125f;
                    P[j * APAD + lane + 32] = d1[r] * 0.125f;
                }
            }
        }
        __syncwarp();

        #pragma unroll
        for (int r = 0; r < 5; r++) {
            int j = w + (r << 3);
            if (j >= U) break;
            float v0 = P[j * APAD + lane], v1 = P[j * APAD + lane + 32];
            float tm = fmaxf(v0, v1);
            #pragma unroll
            for (int o = 16; o > 0; o >>= 1)
                tm = fmaxf(tm, __shfl_xor_sync(0xffffffffu, tm, o));
            float nm = fmaxf(m0[r], tm);
            float p0 = expf(v0 - nm), p1 = expf(v1 - nm);
            float ts = p0 + p1;
            #pragma unroll
            for (int o = 16; o > 0; o >>= 1)
                ts += __shfl_xor_sync(0xffffffffu, ts, o);
            float al = expf(m0[r] - nm);
            s0[r] = s0[r] * al + ts;
            a0[r] *= al; a1[r] *= al;
            m0[r] = nm;
            P[j * APAD + lane]      = p0;
            P[j * APAD + lane + 32] = p1;
        }
        __syncthreads();

        #pragma unroll 4
        for (int k = 0; k < 64; k++) {
            float ve0 = Vt[k * APAD + lane];
            float ve1 = Vt[k * APAD + lane + 32];
            #pragma unroll
            for (int r = 0; r < 5; r++) {
                float pk = P[(w + (r << 3)) * APAD + k];
                a0[r] += pk * ve0;
                a1[r] += pk * ve1;
            }
        }
        __syncthreads();
    }

    #pragma unroll
    for (int r = 0; r < 5; r++) {
        int j = w + (r << 3);
        if (j >= U) break;
        int pidx = (split * NROW + row) * UMAX + j;
        if (lane == 0) { PM[pidx] = m0[r]; PS[pidx] = s0[r]; }
        PA[(size_t)pidx * 64 + lane]      = a0[r];
        PA[(size_t)pidx * 64 + lane + 32] = a1[r];
    }
}

__global__ void attn_merge(const float* __restrict__ PM,
                           const float* __restrict__ PS,
                           const float* __restrict__ PA,
                           const int* __restrict__ top,
                           float* __restrict__ O, int L, int U, int nsplit)
{
    int gw = (blockIdx.x * blockDim.x + threadIdx.x) >> 5;
    int lane = threadIdx.x & 31;
    if (gw >= NROW * U) return;
    int row = gw / U, j = gw % U;
    int b = row / NH, h = row % NH;
    float M = -3.4e38f;
    for (int i = 0; i < nsplit; i++)
        M = fmaxf(M, PM[(i * NROW + row) * UMAX + j]);
    float s = 0.f, acc0 = 0.f, acc1 = 0.f;
    for (int i = 0; i < nsplit; i++) {
        int pidx = (i * NROW + row) * UMAX + j;
        float sc = expf(PM[pidx] - M);
        s    += PS[pidx] * sc;
        acc0 += PA[(size_t)pidx * 64 + lane] * sc;
        acc1 += PA[(size_t)pidx * 64 + lane + 32] * sc;
    }
    float inv = 1.f / s;
    int qi = top[row * UMAX + j];
    size_t o = ((size_t)(b * L + qi)) * D_MODEL + h * DH;
    O[o + lane]      = acc0 * inv;
    O[o + lane + 32] = acc1 * inv;
}

// ------------------------- LayerNorm (two-pass variance) --------------------
__global__ void ln_kernel(const float* __restrict__ X, const float* __restrict__ g,
                          const float* __restrict__ b, float* __restrict__ Y)
{
    __shared__ float s1[4], s2[4];
    int row = blockIdx.x, t = threadIdx.x;
    const float4 v = ((const float4*)(X + (size_t)row * D_MODEL))[t];
    float s = v.x + v.y + v.z + v.w;
    #pragma unroll
    for (int o = 16; o > 0; o >>= 1) s += __shfl_xor_sync(0xffffffffu, s, o);
    if ((t & 31) == 0) s1[t >> 5] = s;
    __syncthreads();
    float mean = (s1[0] + s1[1] + s1[2] + s1[3]) * (1.f / 512.f);
    float dx = v.x - mean, dy = v.y - mean, dz = v.z - mean, dw = v.w - mean;
    float ss = dx * dx + dy * dy + dz * dz + dw * dw;
    #pragma unroll
    for (int o = 16; o > 0; o >>= 1) ss += __shfl_xor_sync(0xffffffffu, ss, o);
    if ((t & 31) == 0) s2[t >> 5] = ss;
    __syncthreads();
    float var = (s2[0] + s2[1] + s2[2] + s2[3]) * (1.f / 512.f);
    float inv = 1.f / sqrtf(var + 1e-5f);
    const float4 g4 = ((const float4*)g)[t];
    const float4 b4 = ((const float4*)b)[t];
    float4 o;
    o.x = dx * inv * g4.x + b4.x;
    o.y = dy * inv * g4.y + b4.y;
    o.z = dz * inv * g4.z + b4.z;
    o.w = dw * inv * g4.w + b4.w;
    ((float4*)(Y + (size_t)row * D_MODEL))[t] = o;
}

// ------------------------- conv-distill helpers -----------------------------
// weight relayout: WC[n][j*512+c] = cv_w[n][c][j]
__global__ void wtrans_kernel(const float* __restrict__ cv, float* __restrict__ WC)
{
    int i = blockIdx.x * blockDim.x + threadIdx.x;
    if (i >= D_MODEL * 3 * D_MODEL) return;
    int n = i / 1536, k = i % 1536;
    int j = k / 512, c = k % 512;
    WC[i] = cv[(size_t)n * 1536 + c * 3 + j];
}

__global__ void pool_kernel(const float* __restrict__ Y, float* __restrict__ X,
                            int L)
{
    int Lh = L >> 1;
    int i = blockIdx.x * blockDim.x + threadIdx.x;
    if (i >= BATCH * Lh * 512) return;
    int d = i & 511;
    int m = (i >> 9) % Lh;
    int b = i / (Lh * 512);
    const float* yb = Y + (size_t)b * L * 512 + d;
    float v = fmaxf(yb[(size_t)(2 * m) * 512], yb[(size_t)(2 * m + 1) * 512]);
    if (m > 0) v = fmaxf(v, yb[(size_t)(2 * m - 1) * 512]);
    X[i] = v;
}

// ---------------------------------------------------------------------------
extern "C" void kernel_launch(void* const* d_in, const int* in_sizes, int n_in,
                              void* d_out, int out_size)
{
    (void)in_sizes; (void)n_in; (void)out_size;
    const float* x_enc = (const float*)d_in[0];
    const float* emb_w = (const float*)d_in[1];
    const float* Wq  = (const float*)d_in[2];
    const float* bq  = (const float*)d_in[3];
    const float* Wk  = (const float*)d_in[4];
    const float* bk  = (const float*)d_in[5];
    const float* Wv  = (const float*)d_in[6];
    const float* bv  = (const float*)d_in[7];
    const float* Wo  = (const float*)d_in[8];
    const float* bo  = (const float*)d_in[9];
    const float* ln1g = (const float*)d_in[10];
    const float* ln1b = (const float*)d_in[11];
    const float* W1  = (const float*)d_in[12];
    const float* b1  = (const float*)d_in[13];
    const float* W2  = (const float*)d_in[14];
    const float* b2  = (const float*)d_in[15];
    const float* ln2g = (const float*)d_in[16];
    const float* ln2b = (const float*)d_in[17];
    const float* cvw = (const float*)d_in[18];
    const float* cvb = (const float*)d_in[19];
    const float* bng = (const float*)d_in[20];
    const float* bnb = (const float*)d_in[21];
    const float* ngp = (const float*)d_in[22];
    const float* nbp = (const float*)d_in[23];

    float *X, *XN, *Yb, *Qb, *Kb, *Vb, *Ob, *H1b, *CVb, *WCb;
    float *PEb, *Mb, *VMb, *PMb, *PSb, *PAb;
    int *IDXb, *TOPb;
    cudaGetSymbolAddress((void**)&X,    g_X);
    cudaGetSymbolAddress((void**)&XN,   g_XN);
    cudaGetSymbolAddress((void**)&Yb,   g_Y);
    cudaGetSymbolAddress((void**)&Qb,   g_Q);
    cudaGetSymbolAddress((void**)&Kb,   g_K);
    cudaGetSymbolAddress((void**)&Vb,   g_V);
    cudaGetSymbolAddress((void**)&Ob,   g_O);
    cudaGetSymbolAddress((void**)&H1b,  g_H1);
    cudaGetSymbolAddress((void**)&CVb,  g_CV);
    cudaGetSymbolAddress((void**)&WCb,  g_WC);
    cudaGetSymbolAddress((void**)&PEb,  g_PE);
    cudaGetSymbolAddress((void**)&Mb,   g_M);
    cudaGetSymbolAddress((void**)&VMb,  g_VM);
    cudaGetSymbolAddress((void**)&PMb,  g_PM);
    cudaGetSymbolAddress((void**)&PSb,  g_PS);
    cudaGetSymbolAddress((void**)&PAb,  g_PA);
    cudaGetSymbolAddress((void**)&IDXb, g_IDX);
    cudaGetSymbolAddress((void**)&TOPb, g_TOP);

    const int attn_smem = (UMAX * APAD * 2 + 64 * APAD * 2) * 4;
    cudaFuncSetAttribute(attn_kernel,
                         cudaFuncAttributeMaxDynamicSharedMemorySize, attn_smem);
    cudaFuncSetAttribute(sgemm_kernel,
                         cudaFuncAttributeMaxDynamicSharedMemorySize, GEMM_SMEM);
    cudaFuncSetAttribute(qkv_kernel,
                         cudaFuncAttributeMaxDynamicSharedMemorySize, GEMM_SMEM);

    // launch order: pe(0), embed(1), idx0(2), qkv(3)... so the profiler's
    // fixed capture slot lands on the tcgen05 GEMM.
    pe_kernel<<<(LMAX * 256 + 255) / 256, 256>>>(PEb);
    {
        int total = BATCH * LMAX * D_MODEL;
        embed_kernel<<<(total + 255) / 256, 256>>>(x_enc, emb_w, PEb, X);
    }

    int Ls[3] = {2048, 1024, 512};
    int Us[3] = {40, 35, 35};
    // idx for layer 0 only (needed before layer-0 msample)
    {
        uint32_t f0, f1, k2a, k2b;
        threefry2x32(0u, 42u, 0u, 0u, &f0, &f1);
        threefry2x32(f0, f1, 0u, 1u, &k2a, &k2b);
        int nidx = Ls[0] * Us[0];
        idx_kernel<<<(nidx + 255) / 256, 256>>>(k2a, k2b, nidx,
                                                (unsigned)(Ls[0] - 1), IDXb);
    }

    int L = LMAX;
    for (int layer = 0; layer < 3; layer++) {
        int U = Us[layer];
        int Mrows = BATCH * L;
        dim3 gg(D_MODEL / 128, Mrows / 128);

        const float* wq = Wq + (size_t)layer * 512 * 512;
        const float* wk = Wk + (size_t)layer * 512 * 512;
        const float* wv = Wv + (size_t)layer * 512 * 512;
        const float* wo = Wo + (size_t)layer * 512 * 512;
        const float* w1 = W1 + (size_t)layer * 512 * 512;
        const float* w2 = W2 + (size_t)layer * 512 * 512;
        const int* idxp = IDXb + layer * LMAX * UMAX;

        {
            dim3 gq(D_MODEL / 128, Mrows / 128, 3);
            qkv_kernel<<<gq, GEMM_THREADS, GEMM_SMEM>>>(
                X, wq, wk, wv, bq + layer * 512, bk + layer * 512,
                bv + layer * 512, Qb, Kb, Vb, 512);
        }

        // prefetch idx for the next layers (after layer-0 qkv)
        if (layer == 0) {
            for (int lay = 1; lay < 3; lay++) {
                uint32_t f0, f1, k2a, k2b;
                threefry2x32(0u, 42u, 0u, (uint32_t)lay, &f0, &f1);
                threefry2x32(f0, f1, 0u, 1u, &k2a, &k2b);
                int nidx = Ls[lay] * Us[lay];
                idx_kernel<<<(nidx + 255) / 256, 256>>>(
                    k2a, k2b, nidx, (unsigned)(Ls[lay] - 1),
                    IDXb + lay * LMAX * UMAX);
            }
        }

        int warps = NROW * L;
        msample_kernel<<<(warps * 32 + 255) / 256, 256>>>(Qb, Kb, idxp, Mb, L, U);
        topk_kernel<<<NROW, 256>>>(Mb, TOPb, L, U);
        vmean_kernel<<<NROW, 256>>>(Vb, VMb, L);
        ofill_kernel<<<(Mrows * 512 + 255) / 256, 256>>>(VMb, Ob, Mrows * 512, L);

        {
            int keys = 512;
            int nsplit = L / keys;
            dim3 ag(nsplit, NROW);
            attn_kernel<<<ag, 256, attn_smem>>>(Qb, Kb, Vb, TOPb,
                                                PMb, PSb, PAb, L, U, keys);
            int mw = NROW * U;
            attn_merge<<<(mw * 32 + 255) / 256, 256>>>(PMb, PSb, PAb, TOPb,
                                                       Ob, L, U, nsplit);
        }

        sgemm_kernel<<<gg, GEMM_THREADS, GEMM_SMEM>>>(
            Ob, wo, bo + layer * 512, X, nullptr, nullptr, Yb, 512, 512,
            FLAG_BIAS | FLAG_RES, 0);
        ln_kernel<<<Mrows, 128>>>(Yb, ln1g + layer * 512, ln1b + layer * 512, XN);
        sgemm_kernel<<<gg, GEMM_THREADS, GEMM_SMEM>>>(
            XN, w1, b1 + layer * 512, nullptr, nullptr, nullptr, H1b, 512, 512,
            FLAG_BIAS | FLAG_GELU, 0);
        sgemm_kernel<<<gg, GEMM_THREADS, GEMM_SMEM>>>(
            H1b, w2, b2 + layer * 512, XN, nullptr, nullptr, Yb, 512, 512,
            FLAG_BIAS | FLAG_RES, 0);
        ln_kernel<<<Mrows, 128>>>(Yb, ln2g + layer * 512, ln2b + layer * 512, X);

        if (layer < 2) {
            wtrans_kernel<<<(512 * 1536 + 255) / 256, 256>>>(
                cvw + (size_t)layer * 512 * 1536, WCb);
            sgemm_kernel<<<gg, GEMM_THREADS, GEMM_SMEM>>>(
                X, WCb, cvb + layer * 512, nullptr, bng + layer * 512,
                bnb + layer * 512, CVb, 512, 1536,
                FLAG_BIAS | FLAG_ELU | FLAG_CIRC, L);
            int Lh = L / 2;
            pool_kernel<<<(BATCH * Lh * 512 + 255) / 256, 256>>>(CVb, X, L);
            L = Lh;
        }
    }

    ln_kernel<<<BATCH * L, 128>>>(X, ngp, nbp, (float*)d_out);
}